// round 6
// baseline (speedup 1.0000x reference)
#include <cuda_runtime.h>
#include <cuda_bf16.h>
#include <cstdint>

#define BATCH 2
#define SEQ   2048
#define HDIM  768
#define IDIM  256
#define MTOK  (BATCH * SEQ)   // 4096 tokens

// ---------------------------------------------------------------------------
// Scratch (device globals; no allocation allowed)
// ---------------------------------------------------------------------------
__device__ float g_Q[MTOK * HDIM];
__device__ float g_K[MTOK * HDIM];
__device__ float g_V[MTOK * HDIM];
__device__ float g_attn[MTOK * HDIM];
__device__ float g_h0[MTOK * IDIM];
__device__ float g_qkvs[MTOK * 3 * IDIM];
__device__ float g_sattn[MTOK * IDIM];
__device__ float g_h1[MTOK * IDIM];
__device__ float g_biasS[MTOK];
__device__ float g_biasM[MTOK];

// ---------------------------------------------------------------------------
// Helpers
// ---------------------------------------------------------------------------
__device__ __forceinline__ unsigned f2tf(float f) {
    unsigned r; asm("cvt.rna.tf32.f32 %0, %1;" : "=r"(r) : "f"(f)); return r;
}
__device__ __forceinline__ float ex2(float x) {
    float r; asm("ex2.approx.f32 %0, %1;" : "=f"(r) : "f"(x)); return r;
}
__device__ __forceinline__ void mma8(float c[4], const unsigned* a, const unsigned* b) {
    asm volatile(
        "mma.sync.aligned.m16n8k8.row.col.f32.tf32.tf32.f32 "
        "{%0,%1,%2,%3},{%4,%5,%6,%7},{%8,%9},{%0,%1,%2,%3};"
        : "+f"(c[0]), "+f"(c[1]), "+f"(c[2]), "+f"(c[3])
        : "r"(a[0]), "r"(a[1]), "r"(a[2]), "r"(a[3]), "r"(b[0]), "r"(b[1]));
}

// Fragment-packed layouts (stride 33 fragments per 32-lane region):
//  A-region(mb,ks): 33 x uint4; entry lane=(g*4+tig): [a0,a1,a2,a3] =
//     A[16mb+g][8ks+tig], A[16mb+8+g][..], A[16mb+g][8ks+tig+4], A[+8][+4]
//  B-region(nb,ks): 33 x uint2; entry lane: [b0,b1] =
//     B[8nb+g][8ks+tig], B[8nb+g][8ks+tig+4]

// ---------------------------------------------------------------------------
// mask -> additive bias (scorer attention)
// ---------------------------------------------------------------------------
__global__ void mask_bias_kernel(const int* __restrict__ mask, float* __restrict__ biasS, int n) {
    int i = blockIdx.x * 256 + threadIdx.x;
    if (i < n) biasS[i] = (mask[i] > 0) ? 0.f : -1e9f;
}

// ---------------------------------------------------------------------------
// GEMM v3: C[M,N] = A[M,K] @ W[N,K]^T + bias[N]
// BM x 128 tile, BK=32, 256 thr (warps 2m x 4n), fragment-packed smem,
// register-prefetch double buffer.
// ---------------------------------------------------------------------------
template<int BM>
__global__ __launch_bounds__(256) void gemm3(
    const float* __restrict__ A, const float* __restrict__ W,
    const float* __restrict__ bias, float* __restrict__ C,
    int M, int N, int K)
{
    constexpr int MFRAG = BM / 32;           // m16 frags per warp
    constexpr int NA    = BM / 32;           // A staging iters
    constexpr int ASTG  = (BM / 16) * 4 * 33 * 4;   // uns per A stage
    constexpr int BSTG  = 16 * 4 * 33 * 2;          // uns per B stage
    extern __shared__ unsigned sm3[];
    unsigned* As = sm3;                      // [2][ASTG]
    unsigned* Bs = sm3 + 2 * ASTG;           // [2][BSTG]

    int tid = threadIdx.x, warp = tid >> 5, lane = tid & 31;
    int wmb = (warp & 1) * MFRAG;            // A mb base
    int wnb = (warp >> 1) * 4;               // B nb base
    int bm = blockIdx.y * BM, bn = blockIdx.x * 128;

    float acc[MFRAG][4][4];
    #pragma unroll
    for (int mt = 0; mt < MFRAG; mt++)
        #pragma unroll
        for (int nt = 0; nt < 4; nt++)
            #pragma unroll
            for (int i = 0; i < 4; i++) acc[mt][nt][i] = 0.f;

    int r_a = tid >> 3, c4 = (tid & 7) * 4;  // staging coords (A rows advance by 32/iter)
    float4 apre[NA], bpre[4];

    // prologue: load + store tile 0
    #pragma unroll
    for (int i = 0; i < NA; i++)
        apre[i] = *(const float4*)(A + (size_t)(bm + r_a + i * 32) * K + c4);
    #pragma unroll
    for (int i = 0; i < 4; i++)
        bpre[i] = *(const float4*)(W + (size_t)(bn + r_a + i * 32) * K + c4);

    auto stsA = [&](int stage) {
        #pragma unroll
        for (int i = 0; i < NA; i++) {
            int r = r_a + i * 32;
            int mb = r >> 4, gg = r & 7, rh = (r >> 3) & 1;
            float v[4] = {apre[i].x, apre[i].y, apre[i].z, apre[i].w};
            #pragma unroll
            for (int j = 0; j < 4; j++) {
                int c = c4 + j, ks = c >> 3, tg = c & 3, dh = (c >> 2) & 1;
                As[stage * ASTG + ((mb * 4 + ks) * 33 + gg * 4 + tg) * 4 + dh * 2 + rh] = f2tf(v[j]);
            }
        }
        #pragma unroll
        for (int i = 0; i < 4; i++) {
            int r = r_a + i * 32;
            int nb = r >> 3, gg = r & 7;
            float v[4] = {bpre[i].x, bpre[i].y, bpre[i].z, bpre[i].w};
            #pragma unroll
            for (int j = 0; j < 4; j++) {
                int c = c4 + j, ks = c >> 3, tg = c & 3, dh = (c >> 2) & 1;
                Bs[stage * BSTG + ((nb * 4 + ks) * 33 + gg * 4 + tg) * 2 + dh] = f2tf(v[j]);
            }
        }
    };
    stsA(0);
    __syncthreads();

    int ntiles = K / 32;
    for (int t = 0; t < ntiles; t++) {
        if (t + 1 < ntiles) {
            int k0 = (t + 1) * 32;
            #pragma unroll
            for (int i = 0; i < NA; i++)
                apre[i] = *(const float4*)(A + (size_t)(bm + r_a + i * 32) * K + k0 + c4);
            #pragma unroll
            for (int i = 0; i < 4; i++)
                bpre[i] = *(const float4*)(W + (size_t)(bn + r_a + i * 32) * K + k0 + c4);
        }

        const unsigned* as = As + (t & 1) * ASTG;
        const unsigned* bs = Bs + (t & 1) * BSTG;
        #pragma unroll
        for (int ks = 0; ks < 4; ks++) {
            uint4 af[MFRAG]; uint2 bf[4];
            #pragma unroll
            for (int mt = 0; mt < MFRAG; mt++)
                af[mt] = *(const uint4*)&as[(((wmb + mt) * 4 + ks) * 33 + lane) * 4];
            #pragma unroll
            for (int nt = 0; nt < 4; nt++)
                bf[nt] = *(const uint2*)&bs[(((wnb + nt) * 4 + ks) * 33 + lane) * 2];
            #pragma unroll
            for (int mt = 0; mt < MFRAG; mt++)
                #pragma unroll
                for (int nt = 0; nt < 4; nt++)
                    mma8(acc[mt][nt], (const unsigned*)&af[mt], (const unsigned*)&bf[nt]);
        }
        if (t + 1 < ntiles) stsA((t + 1) & 1);
        __syncthreads();
    }

    int g = lane >> 2, tig = lane & 3;
    #pragma unroll
    for (int mt = 0; mt < MFRAG; mt++) {
        int row0 = bm + (wmb + mt) * 16 + g;
        #pragma unroll
        for (int nt = 0; nt < 4; nt++) {
            int col = bn + (wnb + nt) * 8 + 2 * tig;
            float b0 = __ldg(bias + col), b1 = __ldg(bias + col + 1);
            *(float2*)(C + (size_t)row0 * N + col) =
                make_float2(acc[mt][nt][0] + b0, acc[mt][nt][1] + b1);
            *(float2*)(C + (size_t)(row0 + 8) * N + col) =
                make_float2(acc[mt][nt][2] + b0, acc[mt][nt][3] + b1);
        }
    }
}

// ---------------------------------------------------------------------------
// Flash attention v3: 256 thr / 128 queries, 64-key tiles, fragment-packed
// K/V/Q/P smem, register-prefetch. head_dim = 64.
// smem: Kpack[8nb][8ks] (4224 uns), Vpack (4224), QP (8448: Q staging then
// per-warp P regions), bias (64 f).
// ---------------------------------------------------------------------------
__global__ __launch_bounds__(256) void attn3(
    const float* __restrict__ Qp, const float* __restrict__ Kp,
    const float* __restrict__ Vp, const float* __restrict__ bias,
    float* __restrict__ Op,
    int S, int ld, int q_off, int k_off, int v_off, int o_ld, int o_off)
{
    extern __shared__ unsigned sm[];
    unsigned* KP = sm;               // K pack: ((nb*8+ks)*33 + lane)*2 + half
    unsigned* VP = sm + 4224;        // V pack: same layout (nb=d-block, ks=key-block)
    unsigned* QP = sm + 8448;        // Q/P pack: ((mb*8+ks)*33 + lane)*4 + slot
    float* bsL = (float*)(sm + 16896);

    const float LOG2E = 1.4426950408889634f;
    int b = blockIdx.z, h = blockIdx.y, q0 = blockIdx.x * 128;
    int tid = threadIdx.x, warp = tid >> 5, lane = tid & 31, g = lane >> 2, tig = lane & 3;

    // ---- stage Q (128x64) packed ----
    const float* qbase = Qp + q_off + h * 64;
    #pragma unroll
    for (int i = 0; i < 8; i++) {
        int idx = tid + i * 256; int r = idx >> 4, cc4 = (idx & 15) * 4;
        float4 v = *(const float4*)(qbase + (size_t)(b * S + q0 + r) * ld + cc4);
        int mb = r >> 4, gg = r & 7, rh = (r >> 3) & 1;
        float vv[4] = {v.x, v.y, v.z, v.w};
        #pragma unroll
        for (int j = 0; j < 4; j++) {
            int c = cc4 + j, ks = c >> 3, tg = c & 3, dh = (c >> 2) & 1;
            QP[((mb * 8 + ks) * 33 + gg * 4 + tg) * 4 + dh * 2 + rh] = f2tf(vv[j]);
        }
    }
    __syncthreads();
    uint4 qf[8];
    #pragma unroll
    for (int ks = 0; ks < 8; ks++)
        qf[ks] = *(const uint4*)&QP[((warp * 8 + ks) * 33 + lane) * 4];
    // (each warp hereafter touches only its own QP region — no block sync needed)

    float o[8][4];
    #pragma unroll
    for (int nt = 0; nt < 8; nt++)
        #pragma unroll
        for (int i = 0; i < 4; i++) o[nt][i] = 0.f;
    float m0 = -1e30f, m1 = -1e30f, l0 = 0.f, l1 = 0.f;
    const float sc = 0.125f * LOG2E;

    const float* kbase = Kp + k_off + h * 64;
    const float* vbase = Vp + v_off + h * 64;
    unsigned* PW = QP + warp * 264 * 4;      // warp P region (8 ks x 33 uint4)

    int lr = tid >> 4, lc = (tid & 15) * 4;  // K/V staging coords

    auto stage_kv = [&](const float4 k4[4], const float4 v4[4], float bv) {
        #pragma unroll
        for (int i = 0; i < 4; i++) {
            int key = lr + i * 16;
            int knb = key >> 3, kg = key & 7;
            int vks = key >> 3, vtg = key & 3, vhf = (key >> 2) & 1;
            float kk[4] = {k4[i].x, k4[i].y, k4[i].z, k4[i].w};
            float vv[4] = {v4[i].x, v4[i].y, v4[i].z, v4[i].w};
            #pragma unroll
            for (int j = 0; j < 4; j++) {
                int d = lc + j;
                int ks = d >> 3, tg = d & 3, dh = (d >> 2) & 1;
                KP[((knb * 8 + ks) * 33 + kg * 4 + tg) * 2 + dh] = f2tf(kk[j]);
                int vnb = d >> 3, vg = d & 7;
                VP[((vnb * 8 + vks) * 33 + vg * 4 + vtg) * 2 + vhf] = f2tf(vv[j]);
            }
        }
        if (tid < 64) bsL[tid] = bv * LOG2E;
    };

    // prologue: tile 0
    {
        float4 k4[4], v4[4]; float bv = 0.f;
        #pragma unroll
        for (int i = 0; i < 4; i++) {
            size_t off = (size_t)(b * S + lr + i * 16) * ld + lc;
            k4[i] = *(const float4*)(kbase + off);
            v4[i] = *(const float4*)(vbase + off);
        }
        if (tid < 64) bv = bias[(size_t)b * S + tid];
        stage_kv(k4, v4, bv);
    }
    __syncthreads();

    for (int kt = 0; kt < S; kt += 64) {
        bool nx = (kt + 64) < S;
        float4 kpre[4], vpre[4]; float bpre = 0.f;
        if (nx) {
            #pragma unroll
            for (int i = 0; i < 4; i++) {
                size_t off = (size_t)(b * S + kt + 64 + lr + i * 16) * ld + lc;
                kpre[i] = *(const float4*)(kbase + off);
                vpre[i] = *(const float4*)(vbase + off);
            }
            if (tid < 64) bpre = bias[(size_t)b * S + kt + 64 + tid];
        }

        // ---- S = Q K^T ----
        float sa[8][4];
        #pragma unroll
        for (int nt = 0; nt < 8; nt++)
            #pragma unroll
            for (int i = 0; i < 4; i++) sa[nt][i] = 0.f;
        #pragma unroll
        for (int ks = 0; ks < 8; ks++) {
            uint2 bf[8];
            #pragma unroll
            for (int nt = 0; nt < 8; nt++)
                bf[nt] = *(const uint2*)&KP[((nt * 8 + ks) * 33 + lane) * 2];
            #pragma unroll
            for (int nt = 0; nt < 8; nt++)
                mma8(sa[nt], (const unsigned*)&qf[ks], (const unsigned*)&bf[nt]);
        }

        // ---- online softmax (exp2 domain) ----
        float rm0 = -1e30f, rm1 = -1e30f;
        #pragma unroll
        for (int nt = 0; nt < 8; nt++) {
            float bl0 = bsL[nt * 8 + 2 * tig], bl1 = bsL[nt * 8 + 2 * tig + 1];
            sa[nt][0] = sa[nt][0] * sc + bl0;
            sa[nt][1] = sa[nt][1] * sc + bl1;
            sa[nt][2] = sa[nt][2] * sc + bl0;
            sa[nt][3] = sa[nt][3] * sc + bl1;
            rm0 = fmaxf(rm0, fmaxf(sa[nt][0], sa[nt][1]));
            rm1 = fmaxf(rm1, fmaxf(sa[nt][2], sa[nt][3]));
        }
        rm0 = fmaxf(rm0, __shfl_xor_sync(0xffffffffu, rm0, 1));
        rm0 = fmaxf(rm0, __shfl_xor_sync(0xffffffffu, rm0, 2));
        rm1 = fmaxf(rm1, __shfl_xor_sync(0xffffffffu, rm1, 1));
        rm1 = fmaxf(rm1, __shfl_xor_sync(0xffffffffu, rm1, 2));
        float mn0 = fmaxf(m0, rm0), mn1 = fmaxf(m1, rm1);
        float c0 = ex2(m0 - mn0), c1 = ex2(m1 - mn1);
        float rs0 = 0.f, rs1 = 0.f;
        #pragma unroll
        for (int nt = 0; nt < 8; nt++) {
            sa[nt][0] = ex2(sa[nt][0] - mn0);
            sa[nt][1] = ex2(sa[nt][1] - mn0);
            sa[nt][2] = ex2(sa[nt][2] - mn1);
            sa[nt][3] = ex2(sa[nt][3] - mn1);
            rs0 += sa[nt][0] + sa[nt][1];
            rs1 += sa[nt][2] + sa[nt][3];
        }
        rs0 += __shfl_xor_sync(0xffffffffu, rs0, 1);
        rs0 += __shfl_xor_sync(0xffffffffu, rs0, 2);
        rs1 += __shfl_xor_sync(0xffffffffu, rs1, 1);
        rs1 += __shfl_xor_sync(0xffffffffu, rs1, 2);
        l0 = l0 * c0 + rs0; l1 = l1 * c1 + rs1;
        m0 = mn0; m1 = mn1;
        #pragma unroll
        for (int nt = 0; nt < 8; nt++) {
            o[nt][0] *= c0; o[nt][1] *= c0; o[nt][2] *= c1; o[nt][3] *= c1;
        }

        // ---- P -> warp-private packed A-region (stagger nt by g) ----
        {
            int ca = 2 * tig, cb = 2 * tig + 1;
            int ta = ca & 3, da = (ca >> 2) << 1;
            int tb = cb & 3, db = (cb >> 2) << 1;
            #pragma unroll
            for (int nti = 0; nti < 8; nti++) {
                int nt = (nti + g) & 7;
                unsigned* rg = PW + nt * 33 * 4 + g * 16;
                rg[ta * 4 + da + 0] = f2tf(sa[nt][0]);
                rg[tb * 4 + db + 0] = f2tf(sa[nt][1]);
                rg[ta * 4 + da + 1] = f2tf(sa[nt][2]);
                rg[tb * 4 + db + 1] = f2tf(sa[nt][3]);
            }
        }
        __syncwarp();

        // ---- O += P V ----
        #pragma unroll
        for (int ks = 0; ks < 8; ks++) {
            uint4 af = *(const uint4*)&PW[(ks * 33 + lane) * 4];
            uint2 bf2[8];
            #pragma unroll
            for (int nt = 0; nt < 8; nt++)
                bf2[nt] = *(const uint2*)&VP[((nt * 8 + ks) * 33 + lane) * 2];
            #pragma unroll
            for (int nt = 0; nt < 8; nt++)
                mma8(o[nt], (const unsigned*)&af, (const unsigned*)&bf2[nt]);
        }
        __syncthreads();

        if (nx) {
            stage_kv(kpre, vpre, bpre);
            __syncthreads();
        }
    }

    // ---- normalize + write ----
    float inv0 = 1.f / l0, inv1 = 1.f / l1;
    int row0 = b * S + q0 + warp * 16 + g;
    float* ob0 = Op + o_off + h * 64 + (size_t)row0 * o_ld;
    float* ob1 = Op + o_off + h * 64 + (size_t)(row0 + 8) * o_ld;
    #pragma unroll
    for (int nt = 0; nt < 8; nt++) {
        int col = nt * 8 + 2 * tig;
        *(float2*)(ob0 + col) = make_float2(o[nt][0] * inv0, o[nt][1] * inv0);
        *(float2*)(ob1 + col) = make_float2(o[nt][2] * inv1, o[nt][3] * inv1);
    }
}

// ---------------------------------------------------------------------------
// Fused survival MLPs, 8 tokens per block
// ---------------------------------------------------------------------------
__global__ __launch_bounds__(128) void mlp_surv2(
    const float* __restrict__ H, const int* __restrict__ mask,
    const float* __restrict__ nw1, const float* __restrict__ nb1,
    const float* __restrict__ nw2, const float* __restrict__ nb2,
    const float* __restrict__ mw1, const float* __restrict__ mb1,
    const float* __restrict__ mw2, const float* __restrict__ mb2,
    const float* __restrict__ dw1, const float* __restrict__ db1,
    const float* __restrict__ dw2, const float* __restrict__ db2,
    float* __restrict__ biasM)
{
    __shared__ float hs[8][256];
    __shared__ float red[24][128];

    int t = threadIdx.x;
    int tok0 = blockIdx.x * 8;

    #pragma unroll
    for (int i = 0; i < 16; i++) {
        int idx = t + i * 128; int tk = idx >> 8, c = idx & 255;
        hs[tk][c] = H[(size_t)(tok0 + tk) * 256 + c];
    }
    __syncthreads();

    const float* wn = nw1 + (size_t)t * 256;
    const float* wm = mw1 + (size_t)t * 256;
    const float* wd = dw1 + (size_t)t * 256;
    float sn[8], smu[8], sd[8];
    #pragma unroll
    for (int k = 0; k < 8; k++) { sn[k] = 0.f; smu[k] = 0.f; sd[k] = 0.f; }
    for (int i = 0; i < 256; i++) {
        float a = wn[i], bb = wm[i], c = wd[i];
        #pragma unroll
        for (int k = 0; k < 8; k++) {
            float hv = hs[k][i];
            sn[k] += a * hv; smu[k] += bb * hv; sd[k] += c * hv;
        }
    }
    float a1 = nb1[t], a2 = nw2[t], b1 = mb1[t], b2 = mw2[t], c1 = db1[t], c2 = dw2[t];
    #pragma unroll
    for (int k = 0; k < 8; k++) {
        red[k][t]      = fmaxf(sn[k]  + a1, 0.f) * a2;
        red[8 + k][t]  = fmaxf(smu[k] + b1, 0.f) * b2;
        red[16 + k][t] = fmaxf(sd[k]  + c1, 0.f) * c2;
    }
    __syncthreads();

    for (int s2 = 64; s2 > 0; s2 >>= 1) {
        for (int j = t; j < 24 * s2; j += 128) {
            int row = j / s2, c = j % s2;
            red[row][c] += red[row][c + s2];
        }
        __syncthreads();
    }

    if (t < 8) {
        float zn = red[t][0] + nb2[0];
        float zm = red[8 + t][0] + mb2[0];
        float zd = red[16 + t][0] + db2[0];
        float n     = (zn > 20.f) ? zn : log1pf(__expf(zn));
        float mu    = 1.f / (1.f + __expf(-zm));
        float delta = fmaxf(zd, 0.f);
        float surv  = logf(n + 1e-8f) + logf(mu + 1e-8f) - delta;
        biasM[tok0 + t] = 0.1f * surv + ((mask[tok0 + t] > 0) ? 0.f : -1e9f);
    }
}

// ---------------------------------------------------------------------------
// Launch
// ---------------------------------------------------------------------------
extern "C" void kernel_launch(void* const* d_in, const int* in_sizes, int n_in,
                              void* d_out, int out_size)
{
    const float* x        = (const float*)d_in[0];
    const int*   mask     = (const int*)  d_in[1];
    const float* qw = (const float*)d_in[2],  *qb = (const float*)d_in[3];
    const float* kw = (const float*)d_in[4],  *kb = (const float*)d_in[5];
    const float* vw = (const float*)d_in[6],  *vb = (const float*)d_in[7];
    const float* ow = (const float*)d_in[8],  *ob = (const float*)d_in[9];
    const float* sp_w = (const float*)d_in[10], *sp_b = (const float*)d_in[11];
    const float* sa_in_w  = (const float*)d_in[12], *sa_in_b  = (const float*)d_in[13];
    const float* sa_out_w = (const float*)d_in[14], *sa_out_b = (const float*)d_in[15];
    const float* nw1 = (const float*)d_in[16], *nb1 = (const float*)d_in[17];
    const float* nw2 = (const float*)d_in[18], *nb2 = (const float*)d_in[19];
    const float* mw1 = (const float*)d_in[20], *mb1 = (const float*)d_in[21];
    const float* mw2 = (const float*)d_in[22], *mb2 = (const float*)d_in[23];
    const float* dw1 = (const float*)d_in[24], *db1 = (const float*)d_in[25];
    const float* dw2 = (const float*)d_in[26], *db2 = (const float*)d_in[27];
    float* out = (float*)d_out;

    float *Q, *K, *V, *attn, *h0, *qkvs, *sattn, *h1, *biasS, *biasM;
    cudaGetSymbolAddress((void**)&Q,     g_Q);
    cudaGetSymbolAddress((void**)&K,     g_K);
    cudaGetSymbolAddress((void**)&V,     g_V);
    cudaGetSymbolAddress((void**)&attn,  g_attn);
    cudaGetSymbolAddress((void**)&h0,    g_h0);
    cudaGetSymbolAddress((void**)&qkvs,  g_qkvs);
    cudaGetSymbolAddress((void**)&sattn, g_sattn);
    cudaGetSymbolAddress((void**)&h1,    g_h1);
    cudaGetSymbolAddress((void**)&biasS, g_biasS);
    cudaGetSymbolAddress((void**)&biasM, g_biasM);

    const int M = MTOK, S = SEQ, B = BATCH, H = HDIM, I = IDIM;

    const int SM128 = (2 * ((128 / 16) * 4 * 33 * 4) + 2 * (16 * 4 * 33 * 2)) * 4;  // 67584
    const int SM64  = (2 * ((64 / 16) * 4 * 33 * 4)  + 2 * (16 * 4 * 33 * 2)) * 4;  // 50688
    const int SMATT = (16896 + 64) * 4;                                             // 67840

    cudaFuncSetAttribute(gemm3<128>, cudaFuncAttributeMaxDynamicSharedMemorySize, SM128);
    cudaFuncSetAttribute(gemm3<64>,  cudaFuncAttributeMaxDynamicSharedMemorySize, SM64);
    cudaFuncSetAttribute(attn3,      cudaFuncAttributeMaxDynamicSharedMemorySize, SMATT);

    // scorer path
    mask_bias_kernel<<<(M + 255) / 256, 256>>>(mask, biasS, M);
    gemm3<64><<<dim3(I / 128, M / 64), 256, SM64>>>(x, sp_w, sp_b, h0, M, I, H);
    gemm3<128><<<dim3(3 * I / 128, M / 128), 256, SM128>>>(h0, sa_in_w, sa_in_b, qkvs, M, 3 * I, I);
    attn3<<<dim3(S / 128, 4, B), 256, SMATT>>>(qkvs, qkvs, qkvs, biasS, sattn,
                                               S, 3 * I, 0, I, 2 * I, I, 0);
    gemm3<64><<<dim3(I / 128, M / 64), 256, SM64>>>(sattn, sa_out_w, sa_out_b, h1, M, I, I);
    mlp_surv2<<<M / 8, 128>>>(h1, mask, nw1, nb1, nw2, nb2,
                              mw1, mb1, mw2, mb2, dw1, db1, dw2, db2, biasM);

    // main path
    gemm3<128><<<dim3(H / 128, M / 128), 256, SM128>>>(x, qw, qb, Q, M, H, H);
    gemm3<128><<<dim3(H / 128, M / 128), 256, SM128>>>(x, kw, kb, K, M, H, H);
    gemm3<128><<<dim3(H / 128, M / 128), 256, SM128>>>(x, vw, vb, V, M, H, H);
    attn3<<<dim3(S / 128, 12, B), 256, SMATT>>>(Q, K, V, biasM, attn,
                                                S, H, 0, 0, 0, H, 0);
    gemm3<128><<<dim3(H / 128, M / 128), 256, SM128>>>(attn, ow, ob, out, M, H, H);
}

// round 8
// speedup vs baseline: 1.1531x; 1.1531x over previous
#include <cuda_runtime.h>
#include <cuda_bf16.h>
#include <cstdint>

#define BATCH 2
#define SEQ   2048
#define HDIM  768
#define IDIM  256
#define MTOK  (BATCH * SEQ)   // 4096 tokens

// ---------------------------------------------------------------------------
// Scratch (device globals; no allocation allowed)
// ---------------------------------------------------------------------------
__device__ float g_Q[MTOK * HDIM];
__device__ float g_K[MTOK * HDIM];
__device__ float g_V[MTOK * HDIM];
__device__ float g_attn[MTOK * HDIM];
__device__ float g_h0[MTOK * IDIM];
__device__ float g_qkvs[MTOK * 3 * IDIM];
__device__ float g_sattn[MTOK * IDIM];
__device__ float g_h1[MTOK * IDIM];
__device__ float g_biasS[MTOK];
__device__ float g_biasM[MTOK];

// ---------------------------------------------------------------------------
// Helpers
// ---------------------------------------------------------------------------
__device__ __forceinline__ unsigned f2tf(float f) {
    unsigned r; asm("cvt.rna.tf32.f32 %0, %1;" : "=r"(r) : "f"(f)); return r;
}
__device__ __forceinline__ float ex2(float x) {
    float r; asm("ex2.approx.f32 %0, %1;" : "=f"(r) : "f"(x)); return r;
}
__device__ __forceinline__ void mma8(float c[4], const unsigned a[4], const unsigned b[2]) {
    asm volatile(
        "mma.sync.aligned.m16n8k8.row.col.f32.tf32.tf32.f32 "
        "{%0,%1,%2,%3},{%4,%5,%6,%7},{%8,%9},{%0,%1,%2,%3};"
        : "+f"(c[0]), "+f"(c[1]), "+f"(c[2]), "+f"(c[3])
        : "r"(a[0]), "r"(a[1]), "r"(a[2]), "r"(a[3]), "r"(b[0]), "r"(b[1]));
}
__device__ __forceinline__ unsigned s2u(const void* p) {
    return (unsigned)__cvta_generic_to_shared(p);
}
__device__ __forceinline__ void cp16(unsigned dst, const void* src) {
    asm volatile("cp.async.ca.shared.global [%0], [%1], 16;" :: "r"(dst), "l"(src));
}
__device__ __forceinline__ void cp_commit() { asm volatile("cp.async.commit_group;"); }
__device__ __forceinline__ void cp_wait0() { asm volatile("cp.async.wait_group 0;"); }
__device__ __forceinline__ void cp_wait1() { asm volatile("cp.async.wait_group 1;"); }

// ---------------------------------------------------------------------------
// mask -> additive bias (scorer attention)
// ---------------------------------------------------------------------------
__global__ void mask_bias_kernel(const int* __restrict__ mask, float* __restrict__ biasS, int n) {
    int i = blockIdx.x * 256 + threadIdx.x;
    if (i < n) biasS[i] = (mask[i] > 0) ? 0.f : -1e9f;
}

// ---------------------------------------------------------------------------
// GEMM body (R4-proven): C[M,N] = A[M,K] @ W[N,K]^T + bias[N]
// BM x 128 tile, BK=32, 256 threads, cp.async 2-stage, stride-36 smem.
// ---------------------------------------------------------------------------
template<int BM>
__device__ __forceinline__ void gemm_body(
    const float* __restrict__ A, const float* __restrict__ W,
    const float* __restrict__ bias, float* __restrict__ C,
    int M, int N, int K, float* smemf)
{
    constexpr int MFRAG = BM / 32;
    float* As = smemf;                       // [2][BM*36]
    float* Bs = smemf + 2 * BM * 36;         // [2][128*36]

    int tid = threadIdx.x, warp = tid >> 5, lane = tid & 31, g = lane >> 2, tig = lane & 3;
    int wm = (warp & 1) * (BM / 2), wn = (warp >> 1) * 32;
    int bm = blockIdx.y * BM, bn = blockIdx.x * 128;

    float acc[MFRAG][4][4];
    #pragma unroll
    for (int mt = 0; mt < MFRAG; mt++)
        #pragma unroll
        for (int nt = 0; nt < 4; nt++)
            #pragma unroll
            for (int i = 0; i < 4; i++) acc[mt][nt][i] = 0.f;

    auto issue = [&](int stage, int k0) {
        #pragma unroll
        for (int i = 0; i < BM / 32; i++) {
            int idx = tid + i * 256;
            int r = idx >> 3, c4 = (idx & 7) * 4;
            cp16(s2u(&As[stage * BM * 36 + r * 36 + c4]),
                 A + (size_t)(bm + r) * K + k0 + c4);
        }
        #pragma unroll
        for (int i = 0; i < 4; i++) {
            int idx = tid + i * 256;
            int r = idx >> 3, c4 = (idx & 7) * 4;
            cp16(s2u(&Bs[stage * 128 * 36 + r * 36 + c4]),
                 W + (size_t)(bn + r) * K + k0 + c4);
        }
        cp_commit();
    };

    int ntiles = K / 32;
    issue(0, 0);
    for (int t = 0; t < ntiles; t++) {
        if (t + 1 < ntiles) { issue((t + 1) & 1, (t + 1) * 32); cp_wait1(); }
        else                { cp_wait0(); }
        __syncthreads();

        const float* as = As + (t & 1) * BM * 36;
        const float* bs = Bs + (t & 1) * 128 * 36;
        #pragma unroll
        for (int ks = 0; ks < 4; ks++) {
            unsigned af[MFRAG][4], bf[4][2];
            #pragma unroll
            for (int mt = 0; mt < MFRAG; mt++) {
                int r0 = wm + mt * 16 + g;
                af[mt][0] = f2tf(as[r0 * 36 + ks * 8 + tig]);
                af[mt][1] = f2tf(as[(r0 + 8) * 36 + ks * 8 + tig]);
                af[mt][2] = f2tf(as[r0 * 36 + ks * 8 + tig + 4]);
                af[mt][3] = f2tf(as[(r0 + 8) * 36 + ks * 8 + tig + 4]);
            }
            #pragma unroll
            for (int nt = 0; nt < 4; nt++) {
                int r0 = wn + nt * 8 + g;
                bf[nt][0] = f2tf(bs[r0 * 36 + ks * 8 + tig]);
                bf[nt][1] = f2tf(bs[r0 * 36 + ks * 8 + tig + 4]);
            }
            #pragma unroll
            for (int mt = 0; mt < MFRAG; mt++)
                #pragma unroll
                for (int nt = 0; nt < 4; nt++)
                    mma8(acc[mt][nt], af[mt], bf[nt]);
        }
        __syncthreads();
    }

    #pragma unroll
    for (int mt = 0; mt < MFRAG; mt++) {
        int row0 = bm + wm + mt * 16 + g;
        #pragma unroll
        for (int nt = 0; nt < 4; nt++) {
            int col = bn + wn + nt * 8 + 2 * tig;
            float b0 = __ldg(bias + col), b1 = __ldg(bias + col + 1);
            *(float2*)(C + (size_t)row0 * N + col) =
                make_float2(acc[mt][nt][0] + b0, acc[mt][nt][1] + b1);
            *(float2*)(C + (size_t)(row0 + 8) * N + col) =
                make_float2(acc[mt][nt][2] + b0, acc[mt][nt][3] + b1);
        }
    }
}

template<int BM>
__global__ __launch_bounds__(256) void gemm2(
    const float* __restrict__ A, const float* __restrict__ W,
    const float* __restrict__ bias, float* __restrict__ C,
    int M, int N, int K)
{
    extern __shared__ float smemf[];
    gemm_body<BM>(A, W, bias, C, M, N, K, smemf);
}

// Fused Q/K/V projection: blockIdx.z selects weights/bias/output.
__global__ __launch_bounds__(256) void gemm2_qkv(
    const float* __restrict__ A,
    const float* __restrict__ w0, const float* __restrict__ w1, const float* __restrict__ w2,
    const float* __restrict__ b0, const float* __restrict__ b1, const float* __restrict__ b2,
    float* __restrict__ c0, float* __restrict__ c1, float* __restrict__ c2,
    int M, int N, int K)
{
    extern __shared__ float smemf[];
    int z = blockIdx.z;
    const float* W = (z == 0) ? w0 : (z == 1) ? w1 : w2;
    const float* bias = (z == 0) ? b0 : (z == 1) ? b1 : b2;
    float* C = (z == 0) ? c0 : (z == 1) ? c1 : c2;
    gemm_body<128>(A, W, bias, C, M, N, K, smemf);
}

// ---------------------------------------------------------------------------
// Flash attention (R4-proven): 256 thr / 128 queries, 64-key tiles,
// register-prefetch pipeline, head_dim=64.
// ---------------------------------------------------------------------------
__global__ __launch_bounds__(256) void attn2(
    const float* __restrict__ Qp, const float* __restrict__ Kp,
    const float* __restrict__ Vp, const float* __restrict__ bias,
    float* __restrict__ Op,
    int S, int ld, int q_off, int k_off, int v_off, int o_ld, int o_off)
{
    extern __shared__ unsigned sm[];
    unsigned* KV = sm;                   // [128][68]
    unsigned* Ps = sm + 128 * 68;        // [128][68]
    float* bsL = (float*)(sm + 2 * 128 * 68);

    const float LOG2E = 1.4426950408889634f;
    int b = blockIdx.z, h = blockIdx.y, q0 = blockIdx.x * 128;
    int tid = threadIdx.x, warp = tid >> 5, lane = tid & 31, g = lane >> 2, tig = lane & 3;

    const float* qbase = Qp + q_off + h * 64;
    #pragma unroll
    for (int i = 0; i < 8; i++) {
        int idx = tid + i * 256; int r = idx >> 4, s = (idx & 15) * 4;
        float4 v = *(const float4*)(qbase + (size_t)(b * S + q0 + r) * ld + s);
        unsigned* d = &Ps[r * 68 + s];
        d[0] = f2tf(v.x); d[1] = f2tf(v.y); d[2] = f2tf(v.z); d[3] = f2tf(v.w);
    }
    __syncthreads();
    unsigned qf[8][4];
    int qr = warp * 16;
    #pragma unroll
    for (int ks = 0; ks < 8; ks++) {
        qf[ks][0] = Ps[(qr + g) * 68 + ks * 8 + tig];
        qf[ks][1] = Ps[(qr + g + 8) * 68 + ks * 8 + tig];
        qf[ks][2] = Ps[(qr + g) * 68 + ks * 8 + tig + 4];
        qf[ks][3] = Ps[(qr + g + 8) * 68 + ks * 8 + tig + 4];
    }

    float o[8][4];
    #pragma unroll
    for (int nt = 0; nt < 8; nt++)
        #pragma unroll
        for (int i = 0; i < 4; i++) o[nt][i] = 0.f;
    float m0 = -1e30f, m1 = -1e30f, l0 = 0.f, l1 = 0.f;
    const float sc = 0.125f * LOG2E;

    const float* kbase = Kp + k_off + h * 64;
    const float* vbase = Vp + v_off + h * 64;
    unsigned* pw = Ps + warp * 16 * 68;

    int lr = tid >> 4, lc = (tid & 15) * 4;

    #pragma unroll
    for (int i = 0; i < 4; i++) {
        int r = lr + i * 16;
        size_t off = (size_t)(b * S + r) * ld + lc;
        float4 k4 = *(const float4*)(kbase + off);
        unsigned* dk = &KV[r * 68 + lc];
        dk[0] = f2tf(k4.x); dk[1] = f2tf(k4.y); dk[2] = f2tf(k4.z); dk[3] = f2tf(k4.w);
        float4 v4 = *(const float4*)(vbase + off);
        unsigned* dv = &KV[(64 + r) * 68 + lc];
        dv[0] = f2tf(v4.x); dv[1] = f2tf(v4.y); dv[2] = f2tf(v4.z); dv[3] = f2tf(v4.w);
    }
    if (tid < 64) bsL[tid] = bias[(size_t)b * S + tid] * LOG2E;
    __syncthreads();

    for (int kt = 0; kt < S; kt += 64) {
        bool nx = (kt + 64) < S;
        float4 kpre[4], vpre[4]; float bpre = 0.f;
        if (nx) {
            #pragma unroll
            for (int i = 0; i < 4; i++) {
                int r = lr + i * 16;
                size_t off = (size_t)(b * S + kt + 64 + r) * ld + lc;
                kpre[i] = *(const float4*)(kbase + off);
                vpre[i] = *(const float4*)(vbase + off);
            }
            if (tid < 64) bpre = bias[(size_t)b * S + kt + 64 + tid];
        }

        float sa[8][4];
        #pragma unroll
        for (int nt = 0; nt < 8; nt++)
            #pragma unroll
            for (int i = 0; i < 4; i++) sa[nt][i] = 0.f;
        #pragma unroll
        for (int ks = 0; ks < 8; ks++) {
            unsigned bf[8][2];
            #pragma unroll
            for (int nt = 0; nt < 8; nt++) {
                bf[nt][0] = KV[(nt * 8 + g) * 68 + ks * 8 + tig];
                bf[nt][1] = KV[(nt * 8 + g) * 68 + ks * 8 + tig + 4];
            }
            #pragma unroll
            for (int nt = 0; nt < 8; nt++) mma8(sa[nt], qf[ks], bf[nt]);
        }

        float rm0 = -1e30f, rm1 = -1e30f;
        #pragma unroll
        for (int nt = 0; nt < 8; nt++) {
            float bl0 = bsL[nt * 8 + 2 * tig], bl1 = bsL[nt * 8 + 2 * tig + 1];
            sa[nt][0] = sa[nt][0] * sc + bl0;
            sa[nt][1] = sa[nt][1] * sc + bl1;
            sa[nt][2] = sa[nt][2] * sc + bl0;
            sa[nt][3] = sa[nt][3] * sc + bl1;
            rm0 = fmaxf(rm0, fmaxf(sa[nt][0], sa[nt][1]));
            rm1 = fmaxf(rm1, fmaxf(sa[nt][2], sa[nt][3]));
        }
        rm0 = fmaxf(rm0, __shfl_xor_sync(0xffffffffu, rm0, 1));
        rm0 = fmaxf(rm0, __shfl_xor_sync(0xffffffffu, rm0, 2));
        rm1 = fmaxf(rm1, __shfl_xor_sync(0xffffffffu, rm1, 1));
        rm1 = fmaxf(rm1, __shfl_xor_sync(0xffffffffu, rm1, 2));
        float mn0 = fmaxf(m0, rm0), mn1 = fmaxf(m1, rm1);
        float c0 = ex2(m0 - mn0), c1 = ex2(m1 - mn1);
        float rs0 = 0.f, rs1 = 0.f;
        #pragma unroll
        for (int nt = 0; nt < 8; nt++) {
            sa[nt][0] = ex2(sa[nt][0] - mn0);
            sa[nt][1] = ex2(sa[nt][1] - mn0);
            sa[nt][2] = ex2(sa[nt][2] - mn1);
            sa[nt][3] = ex2(sa[nt][3] - mn1);
            rs0 += sa[nt][0] + sa[nt][1];
            rs1 += sa[nt][2] + sa[nt][3];
        }
        rs0 += __shfl_xor_sync(0xffffffffu, rs0, 1);
        rs0 += __shfl_xor_sync(0xffffffffu, rs0, 2);
        rs1 += __shfl_xor_sync(0xffffffffu, rs1, 1);
        rs1 += __shfl_xor_sync(0xffffffffu, rs1, 2);
        l0 = l0 * c0 + rs0; l1 = l1 * c1 + rs1;
        m0 = mn0; m1 = mn1;
        #pragma unroll
        for (int nt = 0; nt < 8; nt++) {
            o[nt][0] *= c0; o[nt][1] *= c0; o[nt][2] *= c1; o[nt][3] *= c1;
        }

        #pragma unroll
        for (int nt = 0; nt < 8; nt++) {
            int cc = nt * 8 + 2 * tig;
            pw[g * 68 + cc]           = f2tf(sa[nt][0]);
            pw[g * 68 + cc + 1]       = f2tf(sa[nt][1]);
            pw[(g + 8) * 68 + cc]     = f2tf(sa[nt][2]);
            pw[(g + 8) * 68 + cc + 1] = f2tf(sa[nt][3]);
        }
        __syncwarp();

        #pragma unroll
        for (int ks = 0; ks < 8; ks++) {
            unsigned af[4];
            af[0] = pw[g * 68 + ks * 8 + tig];
            af[1] = pw[(g + 8) * 68 + ks * 8 + tig];
            af[2] = pw[g * 68 + ks * 8 + tig + 4];
            af[3] = pw[(g + 8) * 68 + ks * 8 + tig + 4];
            #pragma unroll
            for (int nt = 0; nt < 8; nt++) {
                unsigned bf2[2];
                bf2[0] = KV[(64 + ks * 8 + tig) * 68 + nt * 8 + g];
                bf2[1] = KV[(64 + ks * 8 + tig + 4) * 68 + nt * 8 + g];
                mma8(o[nt], af, bf2);
            }
        }
        __syncthreads();

        if (nx) {
            #pragma unroll
            for (int i = 0; i < 4; i++) {
                int r = lr + i * 16;
                unsigned* dk = &KV[r * 68 + lc];
                dk[0] = f2tf(kpre[i].x); dk[1] = f2tf(kpre[i].y);
                dk[2] = f2tf(kpre[i].z); dk[3] = f2tf(kpre[i].w);
                unsigned* dv = &KV[(64 + r) * 68 + lc];
                dv[0] = f2tf(vpre[i].x); dv[1] = f2tf(vpre[i].y);
                dv[2] = f2tf(vpre[i].z); dv[3] = f2tf(vpre[i].w);
            }
            if (tid < 64) bsL[tid] = bpre * LOG2E;
            __syncthreads();
        }
    }

    float inv0 = 1.f / l0, inv1 = 1.f / l1;
    int row0 = b * S + q0 + warp * 16 + g;
    float* ob0 = Op + o_off + h * 64 + (size_t)row0 * o_ld;
    float* ob1 = Op + o_off + h * 64 + (size_t)(row0 + 8) * o_ld;
    #pragma unroll
    for (int nt = 0; nt < 8; nt++) {
        int col = nt * 8 + 2 * tig;
        *(float2*)(ob0 + col) = make_float2(o[nt][0] * inv0, o[nt][1] * inv0);
        *(float2*)(ob1 + col) = make_float2(o[nt][2] * inv1, o[nt][3] * inv1);
    }
}

// ---------------------------------------------------------------------------
// Fused survival MLPs, 8 tokens per block
// ---------------------------------------------------------------------------
__global__ __launch_bounds__(128) void mlp_surv2(
    const float* __restrict__ H, const int* __restrict__ mask,
    const float* __restrict__ nw1, const float* __restrict__ nb1,
    const float* __restrict__ nw2, const float* __restrict__ nb2,
    const float* __restrict__ mw1, const float* __restrict__ mb1,
    const float* __restrict__ mw2, const float* __restrict__ mb2,
    const float* __restrict__ dw1, const float* __restrict__ db1,
    const float* __restrict__ dw2, const float* __restrict__ db2,
    float* __restrict__ biasM)
{
    __shared__ float hs[8][256];
    __shared__ float red[24][128];

    int t = threadIdx.x;
    int tok0 = blockIdx.x * 8;

    #pragma unroll
    for (int i = 0; i < 16; i++) {
        int idx = t + i * 128; int tk = idx >> 8, c = idx & 255;
        hs[tk][c] = H[(size_t)(tok0 + tk) * 256 + c];
    }
    __syncthreads();

    const float* wn = nw1 + (size_t)t * 256;
    const float* wm = mw1 + (size_t)t * 256;
    const float* wd = dw1 + (size_t)t * 256;
    float sn[8], smu[8], sd[8];
    #pragma unroll
    for (int k = 0; k < 8; k++) { sn[k] = 0.f; smu[k] = 0.f; sd[k] = 0.f; }
    for (int i = 0; i < 256; i++) {
        float a = wn[i], bb = wm[i], c = wd[i];
        #pragma unroll
        for (int k = 0; k < 8; k++) {
            float hv = hs[k][i];
            sn[k] += a * hv; smu[k] += bb * hv; sd[k] += c * hv;
        }
    }
    float a1 = nb1[t], a2 = nw2[t], b1 = mb1[t], b2 = mw2[t], c1 = db1[t], c2 = dw2[t];
    #pragma unroll
    for (int k = 0; k < 8; k++) {
        red[k][t]      = fmaxf(sn[k]  + a1, 0.f) * a2;
        red[8 + k][t]  = fmaxf(smu[k] + b1, 0.f) * b2;
        red[16 + k][t] = fmaxf(sd[k]  + c1, 0.f) * c2;
    }
    __syncthreads();

    for (int s2 = 64; s2 > 0; s2 >>= 1) {
        for (int j = t; j < 24 * s2; j += 128) {
            int row = j / s2, c = j % s2;
            red[row][c] += red[row][c + s2];
        }
        __syncthreads();
    }

    if (t < 8) {
        float zn = red[t][0] + nb2[0];
        float zm = red[8 + t][0] + mb2[0];
        float zd = red[16 + t][0] + db2[0];
        float n     = (zn > 20.f) ? zn : log1pf(__expf(zn));
        float mu    = 1.f / (1.f + __expf(-zm));
        float delta = fmaxf(zd, 0.f);
        float surv  = logf(n + 1e-8f) + logf(mu + 1e-8f) - delta;
        biasM[tok0 + t] = 0.1f * surv + ((mask[tok0 + t] > 0) ? 0.f : -1e9f);
    }
}

// ---------------------------------------------------------------------------
// Launch: scorer chain on default stream, fused QKV on side stream (overlap)
// ---------------------------------------------------------------------------
extern "C" void kernel_launch(void* const* d_in, const int* in_sizes, int n_in,
                              void* d_out, int out_size)
{
    const float* x        = (const float*)d_in[0];
    const int*   mask     = (const int*)  d_in[1];
    const float* qw = (const float*)d_in[2],  *qb = (const float*)d_in[3];
    const float* kw = (const float*)d_in[4],  *kb = (const float*)d_in[5];
    const float* vw = (const float*)d_in[6],  *vb = (const float*)d_in[7];
    const float* ow = (const float*)d_in[8],  *ob = (const float*)d_in[9];
    const float* sp_w = (const float*)d_in[10], *sp_b = (const float*)d_in[11];
    const float* sa_in_w  = (const float*)d_in[12], *sa_in_b  = (const float*)d_in[13];
    const float* sa_out_w = (const float*)d_in[14], *sa_out_b = (const float*)d_in[15];
    const float* nw1 = (const float*)d_in[16], *nb1 = (const float*)d_in[17];
    const float* nw2 = (const float*)d_in[18], *nb2 = (const float*)d_in[19];
    const float* mw1 = (const float*)d_in[20], *mb1 = (const float*)d_in[21];
    const float* mw2 = (const float*)d_in[22], *mb2 = (const float*)d_in[23];
    const float* dw1 = (const float*)d_in[24], *db1 = (const float*)d_in[25];
    const float* dw2 = (const float*)d_in[26], *db2 = (const float*)d_in[27];
    float* out = (float*)d_out;

    float *Q, *K, *V, *attn, *h0, *qkvs, *sattn, *h1, *biasS, *biasM;
    cudaGetSymbolAddress((void**)&Q,     g_Q);
    cudaGetSymbolAddress((void**)&K,     g_K);
    cudaGetSymbolAddress((void**)&V,     g_V);
    cudaGetSymbolAddress((void**)&attn,  g_attn);
    cudaGetSymbolAddress((void**)&h0,    g_h0);
    cudaGetSymbolAddress((void**)&qkvs,  g_qkvs);
    cudaGetSymbolAddress((void**)&sattn, g_sattn);
    cudaGetSymbolAddress((void**)&h1,    g_h1);
    cudaGetSymbolAddress((void**)&biasS, g_biasS);
    cudaGetSymbolAddress((void**)&biasM, g_biasM);

    const int M = MTOK, S = SEQ, B = BATCH, H = HDIM, I = IDIM;

    const int SM128 = (2 * 128 * 36 + 2 * 128 * 36) * 4;   // 73728
    const int SM64  = (2 * 64 * 36 + 2 * 128 * 36) * 4;    // 55296
    const int SMATT = (2 * 128 * 68 + 64) * 4;             // 69888

    // one-time resource init (streams/events are not device memory)
    static cudaStream_t s1 = nullptr;
    static cudaEvent_t eFork = nullptr, eJoin = nullptr;
    static bool init_done = false, use_streams = false;
    if (!init_done) {
        use_streams =
            (cudaStreamCreateWithFlags(&s1, cudaStreamNonBlocking) == cudaSuccess) &&
            (cudaEventCreateWithFlags(&eFork, cudaEventDisableTiming) == cudaSuccess) &&
            (cudaEventCreateWithFlags(&eJoin, cudaEventDisableTiming) == cudaSuccess);
        cudaFuncSetAttribute(gemm2<128>, cudaFuncAttributeMaxDynamicSharedMemorySize, SM128);
        cudaFuncSetAttribute(gemm2_qkv,  cudaFuncAttributeMaxDynamicSharedMemorySize, SM128);
        cudaFuncSetAttribute(gemm2<64>,  cudaFuncAttributeMaxDynamicSharedMemorySize, SM64);
        cudaFuncSetAttribute(attn2,      cudaFuncAttributeMaxDynamicSharedMemorySize, SMATT);
        init_done = true;
    }

    if (use_streams) {
        // fork: QKV projection on s1 (depends only on x)
        cudaEventRecord(eFork, 0);
        cudaStreamWaitEvent(s1, eFork, 0);
        gemm2_qkv<<<dim3(H / 128, M / 128, 3), 256, SM128, s1>>>(
            x, qw, kw, vw, qb, kb, vb, Q, K, V, M, H, H);
        cudaEventRecord(eJoin, s1);
    } else {
        gemm2_qkv<<<dim3(H / 128, M / 128, 3), 256, SM128>>>(
            x, qw, kw, vw, qb, kb, vb, Q, K, V, M, H, H);
    }

    // scorer chain on default stream (concurrent with QKV when streams work)
    mask_bias_kernel<<<(M + 255) / 256, 256>>>(mask, biasS, M);
    gemm2<64><<<dim3(I / 128, M / 64), 256, SM64>>>(x, sp_w, sp_b, h0, M, I, H);
    gemm2<128><<<dim3(3 * I / 128, M / 128), 256, SM128>>>(h0, sa_in_w, sa_in_b, qkvs, M, 3 * I, I);
    attn2<<<dim3(S / 128, 4, B), 256, SMATT>>>(qkvs, qkvs, qkvs, biasS, sattn,
                                               S, 3 * I, 0, I, 2 * I, I, 0);
    gemm2<64><<<dim3(I / 128, M / 64), 256, SM64>>>(sattn, sa_out_w, sa_out_b, h1, M, I, I);
    mlp_surv2<<<M / 8, 128>>>(h1, mask, nw1, nb1, nw2, nb2,
                              mw1, mb1, mw2, mb2, dw1, db1, dw2, db2, biasM);

    // join, then main attention + output projection
    if (use_streams) cudaStreamWaitEvent(0, eJoin, 0);
    attn2<<<dim3(S / 128, 12, B), 256, SMATT>>>(Q, K, V, biasM, attn,
                                                S, H, 0, 0, 0, H, 0);
    gemm2<128><<<dim3(H / 128, M / 128), 256, SM128>>>(attn, ow, ob, out, M, H, H);
}

// round 9
// speedup vs baseline: 1.2082x; 1.0478x over previous
#include <cuda_runtime.h>
#include <cuda_bf16.h>
#include <cstdint>

#define BATCH 2
#define SEQ   2048
#define HDIM  768
#define IDIM  256
#define MTOK  (BATCH * SEQ)   // 4096 tokens

// ---------------------------------------------------------------------------
// Scratch (device globals; no allocation allowed)
// ---------------------------------------------------------------------------
__device__ float g_Q[MTOK * HDIM];
__device__ float g_K[MTOK * HDIM];
__device__ float g_V[MTOK * HDIM];
__device__ float g_attn[MTOK * HDIM];
__device__ float g_h0[MTOK * IDIM];
__device__ float g_qkvs[MTOK * 3 * IDIM];
__device__ float g_sattn[MTOK * IDIM];
__device__ float g_h1[MTOK * IDIM];
__device__ float g_biasS[MTOK];
__device__ float g_biasM[MTOK];

// ---------------------------------------------------------------------------
// Helpers
// ---------------------------------------------------------------------------
__device__ __forceinline__ unsigned f2tf(float f) {
    unsigned r; asm("cvt.rna.tf32.f32 %0, %1;" : "=r"(r) : "f"(f)); return r;
}
__device__ __forceinline__ float ex2(float x) {
    float r; asm("ex2.approx.f32 %0, %1;" : "=f"(r) : "f"(x)); return r;
}
__device__ __forceinline__ void mma8(float c[4], const unsigned a[4], const unsigned b[2]) {
    asm volatile(
        "mma.sync.aligned.m16n8k8.row.col.f32.tf32.tf32.f32 "
        "{%0,%1,%2,%3},{%4,%5,%6,%7},{%8,%9},{%0,%1,%2,%3};"
        : "+f"(c[0]), "+f"(c[1]), "+f"(c[2]), "+f"(c[3])
        : "r"(a[0]), "r"(a[1]), "r"(a[2]), "r"(a[3]), "r"(b[0]), "r"(b[1]));
}
__device__ __forceinline__ unsigned s2u(const void* p) {
    return (unsigned)__cvta_generic_to_shared(p);
}
__device__ __forceinline__ void cp16(unsigned dst, const void* src) {
    asm volatile("cp.async.ca.shared.global [%0], [%1], 16;" :: "r"(dst), "l"(src));
}
__device__ __forceinline__ void cp_commit() { asm volatile("cp.async.commit_group;"); }
__device__ __forceinline__ void cp_wait0() { asm volatile("cp.async.wait_group 0;"); }
__device__ __forceinline__ void cp_wait1() { asm volatile("cp.async.wait_group 1;"); }

// ---------------------------------------------------------------------------
// mask -> additive bias (scorer attention)
// ---------------------------------------------------------------------------
__global__ void mask_bias_kernel(const int* __restrict__ mask, float* __restrict__ biasS, int n) {
    int i = blockIdx.x * 256 + threadIdx.x;
    if (i < n) biasS[i] = (mask[i] > 0) ? 0.f : -1e9f;
}

// ---------------------------------------------------------------------------
// GEMM body: C[M,N] = A[M,K] @ W[N,K]^T + bias[N]
// BM x 128 tile, BK=32, 256 threads, cp.async 2-stage, stride-36 smem.
// ---------------------------------------------------------------------------
template<int BM>
__device__ __forceinline__ void gemm_body(
    const float* __restrict__ A, const float* __restrict__ W,
    const float* __restrict__ bias, float* __restrict__ C,
    int M, int N, int K, float* smemf)
{
    constexpr int MFRAG = BM / 32;
    float* As = smemf;                       // [2][BM*36]
    float* Bs = smemf + 2 * BM * 36;         // [2][128*36]

    int tid = threadIdx.x, warp = tid >> 5, lane = tid & 31, g = lane >> 2, tig = lane & 3;
    int wm = (warp & 1) * (BM / 2), wn = (warp >> 1) * 32;
    int bm = blockIdx.y * BM, bn = blockIdx.x * 128;

    float acc[MFRAG][4][4];
    #pragma unroll
    for (int mt = 0; mt < MFRAG; mt++)
        #pragma unroll
        for (int nt = 0; nt < 4; nt++)
            #pragma unroll
            for (int i = 0; i < 4; i++) acc[mt][nt][i] = 0.f;

    auto issue = [&](int stage, int k0) {
        #pragma unroll
        for (int i = 0; i < BM / 32; i++) {
            int idx = tid + i * 256;
            int r = idx >> 3, c4 = (idx & 7) * 4;
            cp16(s2u(&As[stage * BM * 36 + r * 36 + c4]),
                 A + (size_t)(bm + r) * K + k0 + c4);
        }
        #pragma unroll
        for (int i = 0; i < 4; i++) {
            int idx = tid + i * 256;
            int r = idx >> 3, c4 = (idx & 7) * 4;
            cp16(s2u(&Bs[stage * 128 * 36 + r * 36 + c4]),
                 W + (size_t)(bn + r) * K + k0 + c4);
        }
        cp_commit();
    };

    int ntiles = K / 32;
    issue(0, 0);
    for (int t = 0; t < ntiles; t++) {
        if (t + 1 < ntiles) { issue((t + 1) & 1, (t + 1) * 32); cp_wait1(); }
        else                { cp_wait0(); }
        __syncthreads();

        const float* as = As + (t & 1) * BM * 36;
        const float* bs = Bs + (t & 1) * 128 * 36;
        #pragma unroll
        for (int ks = 0; ks < 4; ks++) {
            unsigned af[MFRAG][4], bf[4][2];
            #pragma unroll
            for (int mt = 0; mt < MFRAG; mt++) {
                int r0 = wm + mt * 16 + g;
                af[mt][0] = f2tf(as[r0 * 36 + ks * 8 + tig]);
                af[mt][1] = f2tf(as[(r0 + 8) * 36 + ks * 8 + tig]);
                af[mt][2] = f2tf(as[r0 * 36 + ks * 8 + tig + 4]);
                af[mt][3] = f2tf(as[(r0 + 8) * 36 + ks * 8 + tig + 4]);
            }
            #pragma unroll
            for (int nt = 0; nt < 4; nt++) {
                int r0 = wn + nt * 8 + g;
                bf[nt][0] = f2tf(bs[r0 * 36 + ks * 8 + tig]);
                bf[nt][1] = f2tf(bs[r0 * 36 + ks * 8 + tig + 4]);
            }
            #pragma unroll
            for (int mt = 0; mt < MFRAG; mt++)
                #pragma unroll
                for (int nt = 0; nt < 4; nt++)
                    mma8(acc[mt][nt], af[mt], bf[nt]);
        }
        __syncthreads();
    }

    #pragma unroll
    for (int mt = 0; mt < MFRAG; mt++) {
        int row0 = bm + wm + mt * 16 + g;
        #pragma unroll
        for (int nt = 0; nt < 4; nt++) {
            int col = bn + wn + nt * 8 + 2 * tig;
            float b0 = __ldg(bias + col), b1 = __ldg(bias + col + 1);
            *(float2*)(C + (size_t)row0 * N + col) =
                make_float2(acc[mt][nt][0] + b0, acc[mt][nt][1] + b1);
            *(float2*)(C + (size_t)(row0 + 8) * N + col) =
                make_float2(acc[mt][nt][2] + b0, acc[mt][nt][3] + b1);
        }
    }
}

template<int BM>
__global__ __launch_bounds__(256, 2) void gemm2(
    const float* __restrict__ A, const float* __restrict__ W,
    const float* __restrict__ bias, float* __restrict__ C,
    int M, int N, int K)
{
    extern __shared__ float smemf[];
    gemm_body<BM>(A, W, bias, C, M, N, K, smemf);
}

// Fused Q/K/V projection: blockIdx.z selects weights/bias/output.
__global__ __launch_bounds__(256, 2) void gemm2_qkv(
    const float* __restrict__ A,
    const float* __restrict__ w0, const float* __restrict__ w1, const float* __restrict__ w2,
    const float* __restrict__ b0, const float* __restrict__ b1, const float* __restrict__ b2,
    float* __restrict__ c0, float* __restrict__ c1, float* __restrict__ c2,
    int M, int N, int K)
{
    extern __shared__ float smemf[];
    int z = blockIdx.z;
    const float* W = (z == 0) ? w0 : (z == 1) ? w1 : w2;
    const float* bias = (z == 0) ? b0 : (z == 1) ? b1 : b2;
    float* C = (z == 0) ? c0 : (z == 1) ? c1 : c2;
    gemm_body<128>(A, W, bias, C, M, N, K, smemf);
}

// ---------------------------------------------------------------------------
// Flash attention v4: 256 thr / 128 queries, 64-key tiles, cp.async 2-stage
// K/V staging (raw fp32, f2tf at fragment load), 2 CTAs/SM target.
// smem (floats): KVs[2][128*68] (K rows 0-63, V rows 64-127), Ps[128*68]
// (Q staging then per-warp P, tf32 bits), bsL[2][64].
// ---------------------------------------------------------------------------
__global__ __launch_bounds__(256, 2) void attn4(
    const float* __restrict__ Qp, const float* __restrict__ Kp,
    const float* __restrict__ Vp, const float* __restrict__ bias,
    float* __restrict__ Op,
    int S, int ld, int q_off, int k_off, int v_off, int o_ld, int o_off)
{
    extern __shared__ float smf[];
    float* KVs = smf;                              // [2][8704]
    unsigned* Ps = (unsigned*)(smf + 2 * 8704);    // [8704]
    float* bsL = smf + 3 * 8704;                   // [2][64]

    const float LOG2E = 1.4426950408889634f;
    int b = blockIdx.z, h = blockIdx.y, q0 = blockIdx.x * 128;
    int tid = threadIdx.x, warp = tid >> 5, lane = tid & 31, g = lane >> 2, tig = lane & 3;

    // ---- stage Q (128x64) as tf32 into Ps, load persistent fragments ----
    const float* qbase = Qp + q_off + h * 64;
    #pragma unroll
    for (int i = 0; i < 8; i++) {
        int idx = tid + i * 256; int r = idx >> 4, s = (idx & 15) * 4;
        float4 v = *(const float4*)(qbase + (size_t)(b * S + q0 + r) * ld + s);
        unsigned* d = &Ps[r * 68 + s];
        d[0] = f2tf(v.x); d[1] = f2tf(v.y); d[2] = f2tf(v.z); d[3] = f2tf(v.w);
    }
    __syncthreads();
    unsigned qf[8][4];
    int qr = warp * 16;
    #pragma unroll
    for (int ks = 0; ks < 8; ks++) {
        qf[ks][0] = Ps[(qr + g) * 68 + ks * 8 + tig];
        qf[ks][1] = Ps[(qr + g + 8) * 68 + ks * 8 + tig];
        qf[ks][2] = Ps[(qr + g) * 68 + ks * 8 + tig + 4];
        qf[ks][3] = Ps[(qr + g + 8) * 68 + ks * 8 + tig + 4];
    }
    // each warp hereafter touches only its own Ps region (rows qr..qr+15)

    float o[8][4];
    #pragma unroll
    for (int nt = 0; nt < 8; nt++)
        #pragma unroll
        for (int i = 0; i < 4; i++) o[nt][i] = 0.f;
    float m0 = -1e30f, m1 = -1e30f, l0 = 0.f, l1 = 0.f;
    const float sc = 0.125f * LOG2E;

    const float* kbase = Kp + k_off + h * 64;
    const float* vbase = Vp + v_off + h * 64;
    unsigned* pw = Ps + warp * 16 * 68;

    // cp.async staging: thread covers (r, c) pairs, 4 iters x (K + V)
    auto issue = [&](int st, int kt) {
        #pragma unroll
        for (int i = 0; i < 4; i++) {
            int idx = tid + i * 256;          // 0..1023
            int r = idx >> 4, c = (idx & 15) * 4;
            size_t off = (size_t)(b * S + kt + r) * ld + c;
            cp16(s2u(&KVs[st * 8704 + r * 68 + c]), kbase + off);
            cp16(s2u(&KVs[st * 8704 + (64 + r) * 68 + c]), vbase + off);
        }
        if (tid < 16)
            cp16(s2u(&bsL[st * 64 + tid * 4]), bias + (size_t)b * S + kt + tid * 4);
        cp_commit();
    };

    issue(0, 0);
    int ntile = S / 64;
    for (int t = 0; t < ntile; t++) {
        int st = t & 1;
        if (t + 1 < ntile) { issue(st ^ 1, (t + 1) * 64); cp_wait1(); }
        else               { cp_wait0(); }
        __syncthreads();

        const float* KVf = KVs + st * 8704;
        const float* bsf = bsL + st * 64;

        // ---- S = Q K^T (f2tf on K load) ----
        float sa[8][4];
        #pragma unroll
        for (int nt = 0; nt < 8; nt++)
            #pragma unroll
            for (int i = 0; i < 4; i++) sa[nt][i] = 0.f;
        #pragma unroll
        for (int ks = 0; ks < 8; ks++) {
            unsigned bf[8][2];
            #pragma unroll
            for (int nt = 0; nt < 8; nt++) {
                bf[nt][0] = f2tf(KVf[(nt * 8 + g) * 68 + ks * 8 + tig]);
                bf[nt][1] = f2tf(KVf[(nt * 8 + g) * 68 + ks * 8 + tig + 4]);
            }
            #pragma unroll
            for (int nt = 0; nt < 8; nt++) mma8(sa[nt], qf[ks], bf[nt]);
        }

        // ---- online softmax (exp2 domain) ----
        float rm0 = -1e30f, rm1 = -1e30f;
        #pragma unroll
        for (int nt = 0; nt < 8; nt++) {
            float bl0 = bsf[nt * 8 + 2 * tig] * LOG2E;
            float bl1 = bsf[nt * 8 + 2 * tig + 1] * LOG2E;
            sa[nt][0] = sa[nt][0] * sc + bl0;
            sa[nt][1] = sa[nt][1] * sc + bl1;
            sa[nt][2] = sa[nt][2] * sc + bl0;
            sa[nt][3] = sa[nt][3] * sc + bl1;
            rm0 = fmaxf(rm0, fmaxf(sa[nt][0], sa[nt][1]));
            rm1 = fmaxf(rm1, fmaxf(sa[nt][2], sa[nt][3]));
        }
        rm0 = fmaxf(rm0, __shfl_xor_sync(0xffffffffu, rm0, 1));
        rm0 = fmaxf(rm0, __shfl_xor_sync(0xffffffffu, rm0, 2));
        rm1 = fmaxf(rm1, __shfl_xor_sync(0xffffffffu, rm1, 1));
        rm1 = fmaxf(rm1, __shfl_xor_sync(0xffffffffu, rm1, 2));
        float mn0 = fmaxf(m0, rm0), mn1 = fmaxf(m1, rm1);
        float c0 = ex2(m0 - mn0), c1 = ex2(m1 - mn1);
        float rs0 = 0.f, rs1 = 0.f;
        #pragma unroll
        for (int nt = 0; nt < 8; nt++) {
            sa[nt][0] = ex2(sa[nt][0] - mn0);
            sa[nt][1] = ex2(sa[nt][1] - mn0);
            sa[nt][2] = ex2(sa[nt][2] - mn1);
            sa[nt][3] = ex2(sa[nt][3] - mn1);
            rs0 += sa[nt][0] + sa[nt][1];
            rs1 += sa[nt][2] + sa[nt][3];
        }
        rs0 += __shfl_xor_sync(0xffffffffu, rs0, 1);
        rs0 += __shfl_xor_sync(0xffffffffu, rs0, 2);
        rs1 += __shfl_xor_sync(0xffffffffu, rs1, 1);
        rs1 += __shfl_xor_sync(0xffffffffu, rs1, 2);
        l0 = l0 * c0 + rs0; l1 = l1 * c1 + rs1;
        m0 = mn0; m1 = mn1;
        #pragma unroll
        for (int nt = 0; nt < 8; nt++) {
            o[nt][0] *= c0; o[nt][1] *= c0; o[nt][2] *= c1; o[nt][3] *= c1;
        }

        // ---- P -> warp-private smem (tf32) ----
        #pragma unroll
        for (int nt = 0; nt < 8; nt++) {
            int cc = nt * 8 + 2 * tig;
            pw[g * 68 + cc]           = f2tf(sa[nt][0]);
            pw[g * 68 + cc + 1]       = f2tf(sa[nt][1]);
            pw[(g + 8) * 68 + cc]     = f2tf(sa[nt][2]);
            pw[(g + 8) * 68 + cc + 1] = f2tf(sa[nt][3]);
        }
        __syncwarp();

        // ---- O += P V (f2tf on V load) ----
        #pragma unroll
        for (int ks = 0; ks < 8; ks++) {
            unsigned af[4];
            af[0] = pw[g * 68 + ks * 8 + tig];
            af[1] = pw[(g + 8) * 68 + ks * 8 + tig];
            af[2] = pw[g * 68 + ks * 8 + tig + 4];
            af[3] = pw[(g + 8) * 68 + ks * 8 + tig + 4];
            #pragma unroll
            for (int nt = 0; nt < 8; nt++) {
                unsigned bf2[2];
                bf2[0] = f2tf(KVf[(64 + ks * 8 + tig) * 68 + nt * 8 + g]);
                bf2[1] = f2tf(KVf[(64 + ks * 8 + tig + 4) * 68 + nt * 8 + g]);
                mma8(o[nt], af, bf2);
            }
        }
        __syncthreads();   // all warps done reading stage st before it is re-issued
    }

    // ---- normalize + write ----
    float inv0 = 1.f / l0, inv1 = 1.f / l1;
    int row0 = b * S + q0 + warp * 16 + g;
    float* ob0 = Op + o_off + h * 64 + (size_t)row0 * o_ld;
    float* ob1 = Op + o_off + h * 64 + (size_t)(row0 + 8) * o_ld;
    #pragma unroll
    for (int nt = 0; nt < 8; nt++) {
        int col = nt * 8 + 2 * tig;
        *(float2*)(ob0 + col) = make_float2(o[nt][0] * inv0, o[nt][1] * inv0);
        *(float2*)(ob1 + col) = make_float2(o[nt][2] * inv1, o[nt][3] * inv1);
    }
}

// ---------------------------------------------------------------------------
// Fused survival MLPs, 8 tokens per block
// ---------------------------------------------------------------------------
__global__ __launch_bounds__(128) void mlp_surv2(
    const float* __restrict__ H, const int* __restrict__ mask,
    const float* __restrict__ nw1, const float* __restrict__ nb1,
    const float* __restrict__ nw2, const float* __restrict__ nb2,
    const float* __restrict__ mw1, const float* __restrict__ mb1,
    const float* __restrict__ mw2, const float* __restrict__ mb2,
    const float* __restrict__ dw1, const float* __restrict__ db1,
    const float* __restrict__ dw2, const float* __restrict__ db2,
    float* __restrict__ biasM)
{
    __shared__ float hs[8][256];
    __shared__ float red[24][128];

    int t = threadIdx.x;
    int tok0 = blockIdx.x * 8;

    #pragma unroll
    for (int i = 0; i < 16; i++) {
        int idx = t + i * 128; int tk = idx >> 8, c = idx & 255;
        hs[tk][c] = H[(size_t)(tok0 + tk) * 256 + c];
    }
    __syncthreads();

    const float* wn = nw1 + (size_t)t * 256;
    const float* wm = mw1 + (size_t)t * 256;
    const float* wd = dw1 + (size_t)t * 256;
    float sn[8], smu[8], sd[8];
    #pragma unroll
    for (int k = 0; k < 8; k++) { sn[k] = 0.f; smu[k] = 0.f; sd[k] = 0.f; }
    for (int i = 0; i < 256; i++) {
        float a = wn[i], bb = wm[i], c = wd[i];
        #pragma unroll
        for (int k = 0; k < 8; k++) {
            float hv = hs[k][i];
            sn[k] += a * hv; smu[k] += bb * hv; sd[k] += c * hv;
        }
    }
    float a1 = nb1[t], a2 = nw2[t], b1 = mb1[t], b2 = mw2[t], c1 = db1[t], c2 = dw2[t];
    #pragma unroll
    for (int k = 0; k < 8; k++) {
        red[k][t]      = fmaxf(sn[k]  + a1, 0.f) * a2;
        red[8 + k][t]  = fmaxf(smu[k] + b1, 0.f) * b2;
        red[16 + k][t] = fmaxf(sd[k]  + c1, 0.f) * c2;
    }
    __syncthreads();

    for (int s2 = 64; s2 > 0; s2 >>= 1) {
        for (int j = t; j < 24 * s2; j += 128) {
            int row = j / s2, c = j % s2;
            red[row][c] += red[row][c + s2];
        }
        __syncthreads();
    }

    if (t < 8) {
        float zn = red[t][0] + nb2[0];
        float zm = red[8 + t][0] + mb2[0];
        float zd = red[16 + t][0] + db2[0];
        float n     = (zn > 20.f) ? zn : log1pf(__expf(zn));
        float mu    = 1.f / (1.f + __expf(-zm));
        float delta = fmaxf(zd, 0.f);
        float surv  = logf(n + 1e-8f) + logf(mu + 1e-8f) - delta;
        biasM[tok0 + t] = 0.1f * surv + ((mask[tok0 + t] > 0) ? 0.f : -1e9f);
    }
}

// ---------------------------------------------------------------------------
// Launch: scorer chain on default stream, fused QKV on side stream (overlap)
// ---------------------------------------------------------------------------
extern "C" void kernel_launch(void* const* d_in, const int* in_sizes, int n_in,
                              void* d_out, int out_size)
{
    const float* x        = (const float*)d_in[0];
    const int*   mask     = (const int*)  d_in[1];
    const float* qw = (const float*)d_in[2],  *qb = (const float*)d_in[3];
    const float* kw = (const float*)d_in[4],  *kb = (const float*)d_in[5];
    const float* vw = (const float*)d_in[6],  *vb = (const float*)d_in[7];
    const float* ow = (const float*)d_in[8],  *ob = (const float*)d_in[9];
    const float* sp_w = (const float*)d_in[10], *sp_b = (const float*)d_in[11];
    const float* sa_in_w  = (const float*)d_in[12], *sa_in_b  = (const float*)d_in[13];
    const float* sa_out_w = (const float*)d_in[14], *sa_out_b = (const float*)d_in[15];
    const float* nw1 = (const float*)d_in[16], *nb1 = (const float*)d_in[17];
    const float* nw2 = (const float*)d_in[18], *nb2 = (const float*)d_in[19];
    const float* mw1 = (const float*)d_in[20], *mb1 = (const float*)d_in[21];
    const float* mw2 = (const float*)d_in[22], *mb2 = (const float*)d_in[23];
    const float* dw1 = (const float*)d_in[24], *db1 = (const float*)d_in[25];
    const float* dw2 = (const float*)d_in[26], *db2 = (const float*)d_in[27];
    float* out = (float*)d_out;

    float *Q, *K, *V, *attn, *h0, *qkvs, *sattn, *h1, *biasS, *biasM;
    cudaGetSymbolAddress((void**)&Q,     g_Q);
    cudaGetSymbolAddress((void**)&K,     g_K);
    cudaGetSymbolAddress((void**)&V,     g_V);
    cudaGetSymbolAddress((void**)&attn,  g_attn);
    cudaGetSymbolAddress((void**)&h0,    g_h0);
    cudaGetSymbolAddress((void**)&qkvs,  g_qkvs);
    cudaGetSymbolAddress((void**)&sattn, g_sattn);
    cudaGetSymbolAddress((void**)&h1,    g_h1);
    cudaGetSymbolAddress((void**)&biasS, g_biasS);
    cudaGetSymbolAddress((void**)&biasM, g_biasM);

    const int M = MTOK, S = SEQ, B = BATCH, H = HDIM, I = IDIM;

    const int SM128 = (2 * 128 * 36 + 2 * 128 * 36) * 4;   // 73728
    const int SM64  = (2 * 64 * 36 + 2 * 128 * 36) * 4;    // 55296
    const int SMATT = (3 * 8704 + 128) * 4;                // 104960

    // one-time resource init (streams/events are not device memory)
    static cudaStream_t s1 = nullptr;
    static cudaEvent_t eFork = nullptr, eJoin = nullptr;
    static bool init_done = false, use_streams = false;
    if (!init_done) {
        use_streams =
            (cudaStreamCreateWithFlags(&s1, cudaStreamNonBlocking) == cudaSuccess) &&
            (cudaEventCreateWithFlags(&eFork, cudaEventDisableTiming) == cudaSuccess) &&
            (cudaEventCreateWithFlags(&eJoin, cudaEventDisableTiming) == cudaSuccess);
        cudaFuncSetAttribute(gemm2<128>, cudaFuncAttributeMaxDynamicSharedMemorySize, SM128);
        cudaFuncSetAttribute(gemm2_qkv,  cudaFuncAttributeMaxDynamicSharedMemorySize, SM128);
        cudaFuncSetAttribute(gemm2<64>,  cudaFuncAttributeMaxDynamicSharedMemorySize, SM64);
        cudaFuncSetAttribute(attn4,      cudaFuncAttributeMaxDynamicSharedMemorySize, SMATT);
        init_done = true;
    }

    if (use_streams) {
        cudaEventRecord(eFork, 0);
        cudaStreamWaitEvent(s1, eFork, 0);
        gemm2_qkv<<<dim3(H / 128, M / 128, 3), 256, SM128, s1>>>(
            x, qw, kw, vw, qb, kb, vb, Q, K, V, M, H, H);
        cudaEventRecord(eJoin, s1);
    } else {
        gemm2_qkv<<<dim3(H / 128, M / 128, 3), 256, SM128>>>(
            x, qw, kw, vw, qb, kb, vb, Q, K, V, M, H, H);
    }

    // scorer chain on default stream (concurrent with QKV when streams work)
    mask_bias_kernel<<<(M + 255) / 256, 256>>>(mask, biasS, M);
    gemm2<64><<<dim3(I / 128, M / 64), 256, SM64>>>(x, sp_w, sp_b, h0, M, I, H);
    gemm2<128><<<dim3(3 * I / 128, M / 128), 256, SM128>>>(h0, sa_in_w, sa_in_b, qkvs, M, 3 * I, I);
    attn4<<<dim3(S / 128, 4, B), 256, SMATT>>>(qkvs, qkvs, qkvs, biasS, sattn,
                                               S, 3 * I, 0, I, 2 * I, I, 0);
    gemm2<64><<<dim3(I / 128, M / 64), 256, SM64>>>(sattn, sa_out_w, sa_out_b, h1, M, I, I);
    mlp_surv2<<<M / 8, 128>>>(h1, mask, nw1, nb1, nw2, nb2,
                              mw1, mb1, mw2, mb2, dw1, db1, dw2, db2, biasM);

    // join, then main attention + output projection
    if (use_streams) cudaStreamWaitEvent(0, eJoin, 0);
    attn4<<<dim3(S / 128, 12, B), 256, SMATT>>>(Q, K, V, biasM, attn,
                                                S, H, 0, 0, 0, H, 0);
    gemm2<128><<<dim3(H / 128, M / 128), 256, SM128>>>(attn, ow, ob, out, M, H, H);
}

// round 10
// speedup vs baseline: 1.2436x; 1.0293x over previous
#include <cuda_runtime.h>
#include <cuda_bf16.h>
#include <cstdint>

#define BATCH 2
#define SEQ   2048
#define HDIM  768
#define IDIM  256
#define MTOK  (BATCH * SEQ)   // 4096 tokens

// ---------------------------------------------------------------------------
// Scratch (device globals; no allocation allowed)
// Q/K/V and qkvs hold tf32 bit patterns (written by TF32OUT GEMM epilogues).
// ---------------------------------------------------------------------------
__device__ unsigned g_Q[MTOK * HDIM];
__device__ unsigned g_K[MTOK * HDIM];
__device__ unsigned g_V[MTOK * HDIM];
__device__ float    g_attn[MTOK * HDIM];
__device__ float    g_h0[MTOK * IDIM];
__device__ unsigned g_qkvs[MTOK * 3 * IDIM];
__device__ float    g_sattn[MTOK * IDIM];
__device__ float    g_h1[MTOK * IDIM];
__device__ float    g_biasS[MTOK];
__device__ float    g_biasM[MTOK];

// ---------------------------------------------------------------------------
// Helpers
// ---------------------------------------------------------------------------
__device__ __forceinline__ unsigned f2tf(float f) {
    unsigned r; asm("cvt.rna.tf32.f32 %0, %1;" : "=r"(r) : "f"(f)); return r;
}
__device__ __forceinline__ float ex2(float x) {
    float r; asm("ex2.approx.f32 %0, %1;" : "=f"(r) : "f"(x)); return r;
}
__device__ __forceinline__ void mma8(float c[4], const unsigned a[4], const unsigned b[2]) {
    asm volatile(
        "mma.sync.aligned.m16n8k8.row.col.f32.tf32.tf32.f32 "
        "{%0,%1,%2,%3},{%4,%5,%6,%7},{%8,%9},{%0,%1,%2,%3};"
        : "+f"(c[0]), "+f"(c[1]), "+f"(c[2]), "+f"(c[3])
        : "r"(a[0]), "r"(a[1]), "r"(a[2]), "r"(a[3]), "r"(b[0]), "r"(b[1]));
}
__device__ __forceinline__ unsigned s2u(const void* p) {
    return (unsigned)__cvta_generic_to_shared(p);
}
__device__ __forceinline__ void cp16(unsigned dst, const void* src) {
    asm volatile("cp.async.ca.shared.global [%0], [%1], 16;" :: "r"(dst), "l"(src));
}
__device__ __forceinline__ void cp_commit() { asm volatile("cp.async.commit_group;"); }
__device__ __forceinline__ void cp_wait0() { asm volatile("cp.async.wait_group 0;"); }
__device__ __forceinline__ void cp_wait1() { asm volatile("cp.async.wait_group 1;"); }

// ---------------------------------------------------------------------------
// mask -> additive bias (scorer attention)
// ---------------------------------------------------------------------------
__global__ void mask_bias_kernel(const int* __restrict__ mask, float* __restrict__ biasS, int n) {
    int i = blockIdx.x * 256 + threadIdx.x;
    if (i < n) biasS[i] = (mask[i] > 0) ? 0.f : -1e9f;
}

// ---------------------------------------------------------------------------
// GEMM body: C[M,N] = A[M,K] @ W[N,K]^T + bias[N]
// BM x 128 tile, BK=32, 256 threads, cp.async 2-stage, stride-36 smem.
// TF32OUT: store f2tf(acc+bias) bit patterns (for attention consumers).
// ---------------------------------------------------------------------------
template<int BM, bool TF32OUT>
__device__ __forceinline__ void gemm_body(
    const float* __restrict__ A, const float* __restrict__ W,
    const float* __restrict__ bias, void* __restrict__ Cv,
    int M, int N, int K, float* smemf)
{
    constexpr int MFRAG = BM / 32;
    float* As = smemf;                       // [2][BM*36]
    float* Bs = smemf + 2 * BM * 36;         // [2][128*36]

    int tid = threadIdx.x, warp = tid >> 5, lane = tid & 31, g = lane >> 2, tig = lane & 3;
    int wm = (warp & 1) * (BM / 2), wn = (warp >> 1) * 32;
    int bm = blockIdx.y * BM, bn = blockIdx.x * 128;

    float acc[MFRAG][4][4];
    #pragma unroll
    for (int mt = 0; mt < MFRAG; mt++)
        #pragma unroll
        for (int nt = 0; nt < 4; nt++)
            #pragma unroll
            for (int i = 0; i < 4; i++) acc[mt][nt][i] = 0.f;

    auto issue = [&](int stage, int k0) {
        #pragma unroll
        for (int i = 0; i < BM / 32; i++) {
            int idx = tid + i * 256;
            int r = idx >> 3, c4 = (idx & 7) * 4;
            cp16(s2u(&As[stage * BM * 36 + r * 36 + c4]),
                 A + (size_t)(bm + r) * K + k0 + c4);
        }
        #pragma unroll
        for (int i = 0; i < 4; i++) {
            int idx = tid + i * 256;
            int r = idx >> 3, c4 = (idx & 7) * 4;
            cp16(s2u(&Bs[stage * 128 * 36 + r * 36 + c4]),
                 W + (size_t)(bn + r) * K + k0 + c4);
        }
        cp_commit();
    };

    int ntiles = K / 32;
    issue(0, 0);
    for (int t = 0; t < ntiles; t++) {
        if (t + 1 < ntiles) { issue((t + 1) & 1, (t + 1) * 32); cp_wait1(); }
        else                { cp_wait0(); }
        __syncthreads();

        const float* as = As + (t & 1) * BM * 36;
        const float* bs = Bs + (t & 1) * 128 * 36;
        #pragma unroll
        for (int ks = 0; ks < 4; ks++) {
            unsigned af[MFRAG][4], bf[4][2];
            #pragma unroll
            for (int mt = 0; mt < MFRAG; mt++) {
                int r0 = wm + mt * 16 + g;
                af[mt][0] = f2tf(as[r0 * 36 + ks * 8 + tig]);
                af[mt][1] = f2tf(as[(r0 + 8) * 36 + ks * 8 + tig]);
                af[mt][2] = f2tf(as[r0 * 36 + ks * 8 + tig + 4]);
                af[mt][3] = f2tf(as[(r0 + 8) * 36 + ks * 8 + tig + 4]);
            }
            #pragma unroll
            for (int nt = 0; nt < 4; nt++) {
                int r0 = wn + nt * 8 + g;
                bf[nt][0] = f2tf(bs[r0 * 36 + ks * 8 + tig]);
                bf[nt][1] = f2tf(bs[r0 * 36 + ks * 8 + tig + 4]);
            }
            #pragma unroll
            for (int mt = 0; mt < MFRAG; mt++)
                #pragma unroll
                for (int nt = 0; nt < 4; nt++)
                    mma8(acc[mt][nt], af[mt], bf[nt]);
        }
        __syncthreads();
    }

    #pragma unroll
    for (int mt = 0; mt < MFRAG; mt++) {
        int row0 = bm + wm + mt * 16 + g;
        #pragma unroll
        for (int nt = 0; nt < 4; nt++) {
            int col = bn + wn + nt * 8 + 2 * tig;
            float b0 = __ldg(bias + col), b1 = __ldg(bias + col + 1);
            float v00 = acc[mt][nt][0] + b0, v01 = acc[mt][nt][1] + b1;
            float v10 = acc[mt][nt][2] + b0, v11 = acc[mt][nt][3] + b1;
            if (TF32OUT) {
                unsigned* Cu = (unsigned*)Cv;
                *(uint2*)(Cu + (size_t)row0 * N + col) = make_uint2(f2tf(v00), f2tf(v01));
                *(uint2*)(Cu + (size_t)(row0 + 8) * N + col) = make_uint2(f2tf(v10), f2tf(v11));
            } else {
                float* C = (float*)Cv;
                *(float2*)(C + (size_t)row0 * N + col) = make_float2(v00, v01);
                *(float2*)(C + (size_t)(row0 + 8) * N + col) = make_float2(v10, v11);
            }
        }
    }
}

template<int BM, bool TF32OUT>
__global__ __launch_bounds__(256, 2) void gemm2(
    const float* __restrict__ A, const float* __restrict__ W,
    const float* __restrict__ bias, void* __restrict__ C,
    int M, int N, int K)
{
    extern __shared__ float smemf[];
    gemm_body<BM, TF32OUT>(A, W, bias, C, M, N, K, smemf);
}

// Fused Q/K/V projection (tf32 output): blockIdx.z selects weights/bias/output.
__global__ __launch_bounds__(256, 2) void gemm2_qkv(
    const float* __restrict__ A,
    const float* __restrict__ w0, const float* __restrict__ w1, const float* __restrict__ w2,
    const float* __restrict__ b0, const float* __restrict__ b1, const float* __restrict__ b2,
    unsigned* __restrict__ c0, unsigned* __restrict__ c1, unsigned* __restrict__ c2,
    int M, int N, int K)
{
    extern __shared__ float smemf[];
    int z = blockIdx.z;
    const float* W = (z == 0) ? w0 : (z == 1) ? w1 : w2;
    const float* bias = (z == 0) ? b0 : (z == 1) ? b1 : b2;
    unsigned* C = (z == 0) ? c0 : (z == 1) ? c1 : c2;
    gemm_body<128, true>(A, W, bias, C, M, N, K, smemf);
}

// ---------------------------------------------------------------------------
// Flash attention v5: inputs are tf32 bit patterns (no cvt in hot loops).
// 256 thr / 128 queries, 64-key tiles, cp.async 2-stage K/V staging.
// smem (u32): KVs[2][8704], Ps[8704] (Q staging then per-warp P), bsL[2][64].
// ---------------------------------------------------------------------------
__global__ __launch_bounds__(256, 2) void attn5(
    const unsigned* __restrict__ Qp, const unsigned* __restrict__ Kp,
    const unsigned* __restrict__ Vp, const float* __restrict__ bias,
    float* __restrict__ Op,
    int S, int ld, int q_off, int k_off, int v_off, int o_ld, int o_off)
{
    extern __shared__ unsigned smu[];
    unsigned* KVs = smu;                       // [2][8704]
    unsigned* Ps  = smu + 2 * 8704;            // [8704]
    float* bsL    = (float*)(smu + 3 * 8704);  // [2][64]

    const float LOG2E = 1.4426950408889634f;
    int b = blockIdx.z, h = blockIdx.y, q0 = blockIdx.x * 128;
    int tid = threadIdx.x, warp = tid >> 5, lane = tid & 31, g = lane >> 2, tig = lane & 3;

    const unsigned* qbase = Qp + q_off + h * 64;
    const unsigned* kbase = Kp + k_off + h * 64;
    const unsigned* vbase = Vp + v_off + h * 64;

    // ---- stage Q (128x64 tf32) via cp.async ----
    #pragma unroll
    for (int i = 0; i < 8; i++) {
        int idx = tid + i * 256; int r = idx >> 4, s = (idx & 15) * 4;
        cp16(s2u(&Ps[r * 68 + s]), qbase + (size_t)(b * S + q0 + r) * ld + s);
    }
    cp_commit();

    // K/V staging (tf32 bits, no cvt)
    auto issue = [&](int st, int kt) {
        #pragma unroll
        for (int i = 0; i < 4; i++) {
            int idx = tid + i * 256;
            int r = idx >> 4, c = (idx & 15) * 4;
            size_t off = (size_t)(b * S + kt + r) * ld + c;
            cp16(s2u(&KVs[st * 8704 + r * 68 + c]), kbase + off);
            cp16(s2u(&KVs[st * 8704 + (64 + r) * 68 + c]), vbase + off);
        }
        if (tid < 16)
            cp16(s2u(&bsL[st * 64 + tid * 4]), bias + (size_t)b * S + kt + tid * 4);
        cp_commit();
    };

    issue(0, 0);
    cp_wait1();           // Q group retired (KV0 may still be in flight)
    __syncthreads();

    unsigned qf[8][4];
    int qr = warp * 16;
    #pragma unroll
    for (int ks = 0; ks < 8; ks++) {
        qf[ks][0] = Ps[(qr + g) * 68 + ks * 8 + tig];
        qf[ks][1] = Ps[(qr + g + 8) * 68 + ks * 8 + tig];
        qf[ks][2] = Ps[(qr + g) * 68 + ks * 8 + tig + 4];
        qf[ks][3] = Ps[(qr + g + 8) * 68 + ks * 8 + tig + 4];
    }
    // each warp hereafter touches only its own Ps region (rows qr..qr+15)

    float o[8][4];
    #pragma unroll
    for (int nt = 0; nt < 8; nt++)
        #pragma unroll
        for (int i = 0; i < 4; i++) o[nt][i] = 0.f;
    float m0 = -1e30f, m1 = -1e30f, l0 = 0.f, l1 = 0.f;
    const float sc = 0.125f * LOG2E;
    unsigned* pw = Ps + warp * 16 * 68;

    int ntile = S / 64;
    for (int t = 0; t < ntile; t++) {
        int st = t & 1;
        if (t + 1 < ntile) { issue(st ^ 1, (t + 1) * 64); cp_wait1(); }
        else               { cp_wait0(); }
        __syncthreads();

        const unsigned* KVf = KVs + st * 8704;
        const float* bsf = bsL + st * 64;

        // ---- S = Q K^T (pure LDS, no cvt) ----
        float sa[8][4];
        #pragma unroll
        for (int nt = 0; nt < 8; nt++)
            #pragma unroll
            for (int i = 0; i < 4; i++) sa[nt][i] = 0.f;
        #pragma unroll
        for (int ks = 0; ks < 8; ks++) {
            unsigned bf[8][2];
            #pragma unroll
            for (int nt = 0; nt < 8; nt++) {
                bf[nt][0] = KVf[(nt * 8 + g) * 68 + ks * 8 + tig];
                bf[nt][1] = KVf[(nt * 8 + g) * 68 + ks * 8 + tig + 4];
            }
            #pragma unroll
            for (int nt = 0; nt < 8; nt++) mma8(sa[nt], qf[ks], bf[nt]);
        }

        // ---- online softmax (exp2 domain) ----
        float rm0 = -1e30f, rm1 = -1e30f;
        #pragma unroll
        for (int nt = 0; nt < 8; nt++) {
            float bl0 = bsf[nt * 8 + 2 * tig] * LOG2E;
            float bl1 = bsf[nt * 8 + 2 * tig + 1] * LOG2E;
            sa[nt][0] = sa[nt][0] * sc + bl0;
            sa[nt][1] = sa[nt][1] * sc + bl1;
            sa[nt][2] = sa[nt][2] * sc + bl0;
            sa[nt][3] = sa[nt][3] * sc + bl1;
            rm0 = fmaxf(rm0, fmaxf(sa[nt][0], sa[nt][1]));
            rm1 = fmaxf(rm1, fmaxf(sa[nt][2], sa[nt][3]));
        }
        rm0 = fmaxf(rm0, __shfl_xor_sync(0xffffffffu, rm0, 1));
        rm0 = fmaxf(rm0, __shfl_xor_sync(0xffffffffu, rm0, 2));
        rm1 = fmaxf(rm1, __shfl_xor_sync(0xffffffffu, rm1, 1));
        rm1 = fmaxf(rm1, __shfl_xor_sync(0xffffffffu, rm1, 2));
        float mn0 = fmaxf(m0, rm0), mn1 = fmaxf(m1, rm1);
        float c0 = ex2(m0 - mn0), c1 = ex2(m1 - mn1);
        float rs0 = 0.f, rs1 = 0.f;
        #pragma unroll
        for (int nt = 0; nt < 8; nt++) {
            sa[nt][0] = ex2(sa[nt][0] - mn0);
            sa[nt][1] = ex2(sa[nt][1] - mn0);
            sa[nt][2] = ex2(sa[nt][2] - mn1);
            sa[nt][3] = ex2(sa[nt][3] - mn1);
            rs0 += sa[nt][0] + sa[nt][1];
            rs1 += sa[nt][2] + sa[nt][3];
        }
        rs0 += __shfl_xor_sync(0xffffffffu, rs0, 1);
        rs0 += __shfl_xor_sync(0xffffffffu, rs0, 2);
        rs1 += __shfl_xor_sync(0xffffffffu, rs1, 1);
        rs1 += __shfl_xor_sync(0xffffffffu, rs1, 2);
        l0 = l0 * c0 + rs0; l1 = l1 * c1 + rs1;
        m0 = mn0; m1 = mn1;
        #pragma unroll
        for (int nt = 0; nt < 8; nt++) {
            o[nt][0] *= c0; o[nt][1] *= c0; o[nt][2] *= c1; o[nt][3] *= c1;
        }

        // ---- P -> warp-private smem (tf32) ----
        #pragma unroll
        for (int nt = 0; nt < 8; nt++) {
            int cc = nt * 8 + 2 * tig;
            pw[g * 68 + cc]           = f2tf(sa[nt][0]);
            pw[g * 68 + cc + 1]       = f2tf(sa[nt][1]);
            pw[(g + 8) * 68 + cc]     = f2tf(sa[nt][2]);
            pw[(g + 8) * 68 + cc + 1] = f2tf(sa[nt][3]);
        }
        __syncwarp();

        // ---- O += P V (pure LDS, no cvt) ----
        #pragma unroll
        for (int ks = 0; ks < 8; ks++) {
            unsigned af[4];
            af[0] = pw[g * 68 + ks * 8 + tig];
            af[1] = pw[(g + 8) * 68 + ks * 8 + tig];
            af[2] = pw[g * 68 + ks * 8 + tig + 4];
            af[3] = pw[(g + 8) * 68 + ks * 8 + tig + 4];
            #pragma unroll
            for (int nt = 0; nt < 8; nt++) {
                unsigned bf2[2];
                bf2[0] = KVf[(64 + ks * 8 + tig) * 68 + nt * 8 + g];
                bf2[1] = KVf[(64 + ks * 8 + tig + 4) * 68 + nt * 8 + g];
                mma8(o[nt], af, bf2);
            }
        }
        __syncthreads();   // all warps done with stage st before re-issue
    }

    // ---- normalize + write (fp32) ----
    float inv0 = 1.f / l0, inv1 = 1.f / l1;
    int row0 = b * S + q0 + warp * 16 + g;
    float* ob0 = Op + o_off + h * 64 + (size_t)row0 * o_ld;
    float* ob1 = Op + o_off + h * 64 + (size_t)(row0 + 8) * o_ld;
    #pragma unroll
    for (int nt = 0; nt < 8; nt++) {
        int col = nt * 8 + 2 * tig;
        *(float2*)(ob0 + col) = make_float2(o[nt][0] * inv0, o[nt][1] * inv0);
        *(float2*)(ob1 + col) = make_float2(o[nt][2] * inv1, o[nt][3] * inv1);
    }
}

// ---------------------------------------------------------------------------
// Fused survival MLPs, 8 tokens per block
// ---------------------------------------------------------------------------
__global__ __launch_bounds__(128) void mlp_surv2(
    const float* __restrict__ H, const int* __restrict__ mask,
    const float* __restrict__ nw1, const float* __restrict__ nb1,
    const float* __restrict__ nw2, const float* __restrict__ nb2,
    const float* __restrict__ mw1, const float* __restrict__ mb1,
    const float* __restrict__ mw2, const float* __restrict__ mb2,
    const float* __restrict__ dw1, const float* __restrict__ db1,
    const float* __restrict__ dw2, const float* __restrict__ db2,
    float* __restrict__ biasM)
{
    __shared__ float hs[8][256];
    __shared__ float red[24][128];

    int t = threadIdx.x;
    int tok0 = blockIdx.x * 8;

    #pragma unroll
    for (int i = 0; i < 16; i++) {
        int idx = t + i * 128; int tk = idx >> 8, c = idx & 255;
        hs[tk][c] = H[(size_t)(tok0 + tk) * 256 + c];
    }
    __syncthreads();

    const float* wn = nw1 + (size_t)t * 256;
    const float* wm = mw1 + (size_t)t * 256;
    const float* wd = dw1 + (size_t)t * 256;
    float sn[8], smu2[8], sd[8];
    #pragma unroll
    for (int k = 0; k < 8; k++) { sn[k] = 0.f; smu2[k] = 0.f; sd[k] = 0.f; }
    for (int i = 0; i < 256; i++) {
        float a = wn[i], bb = wm[i], c = wd[i];
        #pragma unroll
        for (int k = 0; k < 8; k++) {
            float hv = hs[k][i];
            sn[k] += a * hv; smu2[k] += bb * hv; sd[k] += c * hv;
        }
    }
    float a1 = nb1[t], a2 = nw2[t], b1 = mb1[t], b2 = mw2[t], c1 = db1[t], c2 = dw2[t];
    #pragma unroll
    for (int k = 0; k < 8; k++) {
        red[k][t]      = fmaxf(sn[k]   + a1, 0.f) * a2;
        red[8 + k][t]  = fmaxf(smu2[k] + b1, 0.f) * b2;
        red[16 + k][t] = fmaxf(sd[k]   + c1, 0.f) * c2;
    }
    __syncthreads();

    for (int s2 = 64; s2 > 0; s2 >>= 1) {
        for (int j = t; j < 24 * s2; j += 128) {
            int row = j / s2, c = j % s2;
            red[row][c] += red[row][c + s2];
        }
        __syncthreads();
    }

    if (t < 8) {
        float zn = red[t][0] + nb2[0];
        float zm = red[8 + t][0] + mb2[0];
        float zd = red[16 + t][0] + db2[0];
        float n     = (zn > 20.f) ? zn : log1pf(__expf(zn));
        float mu    = 1.f / (1.f + __expf(-zm));
        float delta = fmaxf(zd, 0.f);
        float surv  = logf(n + 1e-8f) + logf(mu + 1e-8f) - delta;
        biasM[tok0 + t] = 0.1f * surv + ((mask[tok0 + t] > 0) ? 0.f : -1e9f);
    }
}

// ---------------------------------------------------------------------------
// Launch: scorer chain on default stream, fused QKV on side stream (overlap)
// ---------------------------------------------------------------------------
extern "C" void kernel_launch(void* const* d_in, const int* in_sizes, int n_in,
                              void* d_out, int out_size)
{
    const float* x        = (const float*)d_in[0];
    const int*   mask     = (const int*)  d_in[1];
    const float* qw = (const float*)d_in[2],  *qb = (const float*)d_in[3];
    const float* kw = (const float*)d_in[4],  *kb = (const float*)d_in[5];
    const float* vw = (const float*)d_in[6],  *vb = (const float*)d_in[7];
    const float* ow = (const float*)d_in[8],  *ob = (const float*)d_in[9];
    const float* sp_w = (const float*)d_in[10], *sp_b = (const float*)d_in[11];
    const float* sa_in_w  = (const float*)d_in[12], *sa_in_b  = (const float*)d_in[13];
    const float* sa_out_w = (const float*)d_in[14], *sa_out_b = (const float*)d_in[15];
    const float* nw1 = (const float*)d_in[16], *nb1 = (const float*)d_in[17];
    const float* nw2 = (const float*)d_in[18], *nb2 = (const float*)d_in[19];
    const float* mw1 = (const float*)d_in[20], *mb1 = (const float*)d_in[21];
    const float* mw2 = (const float*)d_in[22], *mb2 = (const float*)d_in[23];
    const float* dw1 = (const float*)d_in[24], *db1 = (const float*)d_in[25];
    const float* dw2 = (const float*)d_in[26], *db2 = (const float*)d_in[27];
    float* out = (float*)d_out;

    unsigned *Q, *K, *V, *qkvs;
    float *attn, *h0, *sattn, *h1, *biasS, *biasM;
    cudaGetSymbolAddress((void**)&Q,     g_Q);
    cudaGetSymbolAddress((void**)&K,     g_K);
    cudaGetSymbolAddress((void**)&V,     g_V);
    cudaGetSymbolAddress((void**)&attn,  g_attn);
    cudaGetSymbolAddress((void**)&h0,    g_h0);
    cudaGetSymbolAddress((void**)&qkvs,  g_qkvs);
    cudaGetSymbolAddress((void**)&sattn, g_sattn);
    cudaGetSymbolAddress((void**)&h1,    g_h1);
    cudaGetSymbolAddress((void**)&biasS, g_biasS);
    cudaGetSymbolAddress((void**)&biasM, g_biasM);

    const int M = MTOK, S = SEQ, B = BATCH, H = HDIM, I = IDIM;

    const int SM128 = (2 * 128 * 36 + 2 * 128 * 36) * 4;   // 73728
    const int SM64  = (2 * 64 * 36 + 2 * 128 * 36) * 4;    // 55296
    const int SMATT = (3 * 8704 + 128) * 4;                // 104960

    // one-time resource init (streams/events are not device memory)
    static cudaStream_t s1 = nullptr;
    static cudaEvent_t eFork = nullptr, eJoin = nullptr;
    static bool init_done = false, use_streams = false;
    if (!init_done) {
        use_streams =
            (cudaStreamCreateWithFlags(&s1, cudaStreamNonBlocking) == cudaSuccess) &&
            (cudaEventCreateWithFlags(&eFork, cudaEventDisableTiming) == cudaSuccess) &&
            (cudaEventCreateWithFlags(&eJoin, cudaEventDisableTiming) == cudaSuccess);
        cudaFuncSetAttribute((const void*)gemm2<128, false>, cudaFuncAttributeMaxDynamicSharedMemorySize, SM128);
        cudaFuncSetAttribute((const void*)gemm2<128, true>,  cudaFuncAttributeMaxDynamicSharedMemorySize, SM128);
        cudaFuncSetAttribute((const void*)gemm2_qkv,         cudaFuncAttributeMaxDynamicSharedMemorySize, SM128);
        cudaFuncSetAttribute((const void*)gemm2<64, false>,  cudaFuncAttributeMaxDynamicSharedMemorySize, SM64);
        cudaFuncSetAttribute((const void*)attn5,             cudaFuncAttributeMaxDynamicSharedMemorySize, SMATT);
        init_done = true;
    }

    if (use_streams) {
        cudaEventRecord(eFork, 0);
        cudaStreamWaitEvent(s1, eFork, 0);
        gemm2_qkv<<<dim3(H / 128, M / 128, 3), 256, SM128, s1>>>(
            x, qw, kw, vw, qb, kb, vb, Q, K, V, M, H, H);
        cudaEventRecord(eJoin, s1);
    } else {
        gemm2_qkv<<<dim3(H / 128, M / 128, 3), 256, SM128>>>(
            x, qw, kw, vw, qb, kb, vb, Q, K, V, M, H, H);
    }

    // scorer chain on default stream (concurrent with QKV when streams work)
    mask_bias_kernel<<<(M + 255) / 256, 256>>>(mask, biasS, M);
    gemm2<64, false><<<dim3(I / 128, M / 64), 256, SM64>>>(x, sp_w, sp_b, h0, M, I, H);
    gemm2<128, true><<<dim3(3 * I / 128, M / 128), 256, SM128>>>(h0, sa_in_w, sa_in_b, qkvs, M, 3 * I, I);
    attn5<<<dim3(S / 128, 4, B), 256, SMATT>>>(qkvs, qkvs, qkvs, biasS, sattn,
                                               S, 3 * I, 0, I, 2 * I, I, 0);
    gemm2<64, false><<<dim3(I / 128, M / 64), 256, SM64>>>(sattn, sa_out_w, sa_out_b, h1, M, I, I);
    mlp_surv2<<<M / 8, 128>>>(h1, mask, nw1, nb1, nw2, nb2,
                              mw1, mb1, mw2, mb2, dw1, db1, dw2, db2, biasM);

    // join, then main attention + output projection
    if (use_streams) cudaStreamWaitEvent(0, eJoin, 0);
    attn5<<<dim3(S / 128, 12, B), 256, SMATT>>>(Q, K, V, biasM, attn,
                                                S, H, 0, 0, 0, H, 0);
    gemm2<128, false><<<dim3(H / 128, M / 128), 256, SM128>>>(attn, ow, ob, out, M, H, H);
}

// round 11
// speedup vs baseline: 1.2565x; 1.0104x over previous
#include <cuda_runtime.h>
#include <cuda_bf16.h>
#include <cstdint>

#define BATCH 2
#define SEQ   2048
#define HDIM  768
#define IDIM  256
#define MTOK  (BATCH * SEQ)   // 4096 tokens

// ---------------------------------------------------------------------------
// Scratch (device globals; no allocation allowed)
// *_tf / g_Q.. / g_h0 / g_sattn / g_attn hold tf32 bit patterns.
// ---------------------------------------------------------------------------
__device__ unsigned g_xtf [MTOK * HDIM];
__device__ unsigned g_qwtf[HDIM * HDIM];
__device__ unsigned g_kwtf[HDIM * HDIM];
__device__ unsigned g_vwtf[HDIM * HDIM];
__device__ unsigned g_owtf[HDIM * HDIM];
__device__ unsigned g_spwtf [IDIM * HDIM];
__device__ unsigned g_saiwtf[3 * IDIM * IDIM];
__device__ unsigned g_saowtf[IDIM * IDIM];

__device__ unsigned g_Q[MTOK * HDIM];
__device__ unsigned g_K[MTOK * HDIM];
__device__ unsigned g_V[MTOK * HDIM];
__device__ unsigned g_attn[MTOK * HDIM];
__device__ unsigned g_h0[MTOK * IDIM];
__device__ unsigned g_qkvs[MTOK * 3 * IDIM];
__device__ unsigned g_sattn[MTOK * IDIM];
__device__ float    g_h1[MTOK * IDIM];
__device__ float    g_biasS[MTOK];
__device__ float    g_biasM[MTOK];

// ---------------------------------------------------------------------------
// Helpers
// ---------------------------------------------------------------------------
__device__ __forceinline__ unsigned f2tf(float f) {
    unsigned r; asm("cvt.rna.tf32.f32 %0, %1;" : "=r"(r) : "f"(f)); return r;
}
__device__ __forceinline__ float ex2(float x) {
    float r; asm("ex2.approx.f32 %0, %1;" : "=f"(r) : "f"(x)); return r;
}
__device__ __forceinline__ void mma8(float c[4], const unsigned a[4], const unsigned b[2]) {
    asm volatile(
        "mma.sync.aligned.m16n8k8.row.col.f32.tf32.tf32.f32 "
        "{%0,%1,%2,%3},{%4,%5,%6,%7},{%8,%9},{%0,%1,%2,%3};"
        : "+f"(c[0]), "+f"(c[1]), "+f"(c[2]), "+f"(c[3])
        : "r"(a[0]), "r"(a[1]), "r"(a[2]), "r"(a[3]), "r"(b[0]), "r"(b[1]));
}
__device__ __forceinline__ unsigned s2u(const void* p) {
    return (unsigned)__cvta_generic_to_shared(p);
}
__device__ __forceinline__ void cp16(unsigned dst, const void* src) {
    asm volatile("cp.async.ca.shared.global [%0], [%1], 16;" :: "r"(dst), "l"(src));
}
__device__ __forceinline__ void cp_commit() { asm volatile("cp.async.commit_group;"); }
__device__ __forceinline__ void cp_wait0() { asm volatile("cp.async.wait_group 0;"); }
__device__ __forceinline__ void cp_wait1() { asm volatile("cp.async.wait_group 1;"); }

// ---------------------------------------------------------------------------
// One-shot tf32 conversion of x + all GEMM weights (8 segments, grid.y picks)
// ---------------------------------------------------------------------------
__global__ __launch_bounds__(256) void cvt_tf32_all(
    const float* __restrict__ x,   const float* __restrict__ qw,
    const float* __restrict__ kw,  const float* __restrict__ vw,
    const float* __restrict__ ow,  const float* __restrict__ spw,
    const float* __restrict__ saiw,const float* __restrict__ saow,
    unsigned* __restrict__ xo,  unsigned* __restrict__ qo,
    unsigned* __restrict__ ko,  unsigned* __restrict__ vo,
    unsigned* __restrict__ oo,  unsigned* __restrict__ spo,
    unsigned* __restrict__ saio,unsigned* __restrict__ saoo)
{
    const int seg = blockIdx.y;
    int n;
    const float* s; unsigned* d;
    switch (seg) {
        case 0: s = x;    d = xo;   n = MTOK * HDIM;     break;
        case 1: s = qw;   d = qo;   n = HDIM * HDIM;     break;
        case 2: s = kw;   d = ko;   n = HDIM * HDIM;     break;
        case 3: s = vw;   d = vo;   n = HDIM * HDIM;     break;
        case 4: s = ow;   d = oo;   n = HDIM * HDIM;     break;
        case 5: s = spw;  d = spo;  n = IDIM * HDIM;     break;
        case 6: s = saiw; d = saio; n = 3 * IDIM * IDIM; break;
        default:s = saow; d = saoo; n = IDIM * IDIM;     break;
    }
    int n4 = n >> 2;
    for (int i = blockIdx.x * 256 + threadIdx.x; i < n4; i += gridDim.x * 256) {
        float4 v = ((const float4*)s)[i];
        ((uint4*)d)[i] = make_uint4(f2tf(v.x), f2tf(v.y), f2tf(v.z), f2tf(v.w));
    }
}

// ---------------------------------------------------------------------------
// mask -> additive bias (scorer attention)
// ---------------------------------------------------------------------------
__global__ void mask_bias_kernel(const int* __restrict__ mask, float* __restrict__ biasS, int n) {
    int i = blockIdx.x * 256 + threadIdx.x;
    if (i < n) biasS[i] = (mask[i] > 0) ? 0.f : -1e9f;
}

// ---------------------------------------------------------------------------
// GEMM (tf32-bit inputs): C[M,N] = A[M,K] @ W[N,K]^T + bias[N]
// BM x 128 tile, BK=32, 256 threads, cp.async 2-stage, stride-36 smem,
// ZERO cvt in the inner loop. TF32OUT selects tf32-bit vs fp32 epilogue.
// ---------------------------------------------------------------------------
template<int BM, bool TF32OUT>
__device__ __forceinline__ void gemm_body(
    const unsigned* __restrict__ A, const unsigned* __restrict__ W,
    const float* __restrict__ bias, void* __restrict__ Cv,
    int M, int N, int K, unsigned* smemu)
{
    constexpr int MFRAG = BM / 32;
    unsigned* As = smemu;                      // [2][BM*36]
    unsigned* Bs = smemu + 2 * BM * 36;        // [2][128*36]

    int tid = threadIdx.x, warp = tid >> 5, lane = tid & 31, g = lane >> 2, tig = lane & 3;
    int wm = (warp & 1) * (BM / 2), wn = (warp >> 1) * 32;
    int bm = blockIdx.y * BM, bn = blockIdx.x * 128;

    float acc[MFRAG][4][4];
    #pragma unroll
    for (int mt = 0; mt < MFRAG; mt++)
        #pragma unroll
        for (int nt = 0; nt < 4; nt++)
            #pragma unroll
            for (int i = 0; i < 4; i++) acc[mt][nt][i] = 0.f;

    auto issue = [&](int stage, int k0) {
        #pragma unroll
        for (int i = 0; i < BM / 32; i++) {
            int idx = tid + i * 256;
            int r = idx >> 3, c4 = (idx & 7) * 4;
            cp16(s2u(&As[stage * BM * 36 + r * 36 + c4]),
                 A + (size_t)(bm + r) * K + k0 + c4);
        }
        #pragma unroll
        for (int i = 0; i < 4; i++) {
            int idx = tid + i * 256;
            int r = idx >> 3, c4 = (idx & 7) * 4;
            cp16(s2u(&Bs[stage * 128 * 36 + r * 36 + c4]),
                 W + (size_t)(bn + r) * K + k0 + c4);
        }
        cp_commit();
    };

    int ntiles = K / 32;
    issue(0, 0);
    for (int t = 0; t < ntiles; t++) {
        if (t + 1 < ntiles) { issue((t + 1) & 1, (t + 1) * 32); cp_wait1(); }
        else                { cp_wait0(); }
        __syncthreads();

        const unsigned* as = As + (t & 1) * BM * 36;
        const unsigned* bs = Bs + (t & 1) * 128 * 36;
        #pragma unroll
        for (int ks = 0; ks < 4; ks++) {
            unsigned af[MFRAG][4], bf[4][2];
            #pragma unroll
            for (int mt = 0; mt < MFRAG; mt++) {
                int r0 = wm + mt * 16 + g;
                af[mt][0] = as[r0 * 36 + ks * 8 + tig];
                af[mt][1] = as[(r0 + 8) * 36 + ks * 8 + tig];
                af[mt][2] = as[r0 * 36 + ks * 8 + tig + 4];
                af[mt][3] = as[(r0 + 8) * 36 + ks * 8 + tig + 4];
            }
            #pragma unroll
            for (int nt = 0; nt < 4; nt++) {
                int r0 = wn + nt * 8 + g;
                bf[nt][0] = bs[r0 * 36 + ks * 8 + tig];
                bf[nt][1] = bs[r0 * 36 + ks * 8 + tig + 4];
            }
            #pragma unroll
            for (int mt = 0; mt < MFRAG; mt++)
                #pragma unroll
                for (int nt = 0; nt < 4; nt++)
                    mma8(acc[mt][nt], af[mt], bf[nt]);
        }
        __syncthreads();
    }

    #pragma unroll
    for (int mt = 0; mt < MFRAG; mt++) {
        int row0 = bm + wm + mt * 16 + g;
        #pragma unroll
        for (int nt = 0; nt < 4; nt++) {
            int col = bn + wn + nt * 8 + 2 * tig;
            float b0 = __ldg(bias + col), b1 = __ldg(bias + col + 1);
            float v00 = acc[mt][nt][0] + b0, v01 = acc[mt][nt][1] + b1;
            float v10 = acc[mt][nt][2] + b0, v11 = acc[mt][nt][3] + b1;
            if (TF32OUT) {
                unsigned* Cu = (unsigned*)Cv;
                *(uint2*)(Cu + (size_t)row0 * N + col) = make_uint2(f2tf(v00), f2tf(v01));
                *(uint2*)(Cu + (size_t)(row0 + 8) * N + col) = make_uint2(f2tf(v10), f2tf(v11));
            } else {
                float* C = (float*)Cv;
                *(float2*)(C + (size_t)row0 * N + col) = make_float2(v00, v01);
                *(float2*)(C + (size_t)(row0 + 8) * N + col) = make_float2(v10, v11);
            }
        }
    }
}

template<int BM, bool TF32OUT>
__global__ __launch_bounds__(256, 2) void gemm_u(
    const unsigned* __restrict__ A, const unsigned* __restrict__ W,
    const float* __restrict__ bias, void* __restrict__ C,
    int M, int N, int K)
{
    extern __shared__ unsigned smemu[];
    gemm_body<BM, TF32OUT>(A, W, bias, C, M, N, K, smemu);
}

// Fused Q/K/V projection (tf32-bit in & out): blockIdx.z selects w/b/out.
__global__ __launch_bounds__(256, 2) void gemm_u_qkv(
    const unsigned* __restrict__ A,
    const unsigned* __restrict__ w0, const unsigned* __restrict__ w1, const unsigned* __restrict__ w2,
    const float* __restrict__ b0, const float* __restrict__ b1, const float* __restrict__ b2,
    unsigned* __restrict__ c0, unsigned* __restrict__ c1, unsigned* __restrict__ c2,
    int M, int N, int K)
{
    extern __shared__ unsigned smemu[];
    int z = blockIdx.z;
    const unsigned* W = (z == 0) ? w0 : (z == 1) ? w1 : w2;
    const float* bias = (z == 0) ? b0 : (z == 1) ? b1 : b2;
    unsigned* C = (z == 0) ? c0 : (z == 1) ? c1 : c2;
    gemm_body<128, true>(A, W, bias, C, M, N, K, smemu);
}

// ---------------------------------------------------------------------------
// Flash attention v5 (tf32-bit inputs, no cvt in hot loops).
// 256 thr / 128 queries, 64-key tiles, cp.async 2-stage K/V staging.
// TF32OUT: write tf32 bits (for GEMM consumers) vs fp32.
// ---------------------------------------------------------------------------
template<bool TF32OUT>
__global__ __launch_bounds__(256, 2) void attn5(
    const unsigned* __restrict__ Qp, const unsigned* __restrict__ Kp,
    const unsigned* __restrict__ Vp, const float* __restrict__ bias,
    void* __restrict__ Opv,
    int S, int ld, int q_off, int k_off, int v_off, int o_ld, int o_off)
{
    extern __shared__ unsigned smu[];
    unsigned* KVs = smu;                       // [2][8704]
    unsigned* Ps  = smu + 2 * 8704;            // [8704]
    float* bsL    = (float*)(smu + 3 * 8704);  // [2][64]

    const float LOG2E = 1.4426950408889634f;
    int b = blockIdx.z, h = blockIdx.y, q0 = blockIdx.x * 128;
    int tid = threadIdx.x, warp = tid >> 5, lane = tid & 31, g = lane >> 2, tig = lane & 3;

    const unsigned* qbase = Qp + q_off + h * 64;
    const unsigned* kbase = Kp + k_off + h * 64;
    const unsigned* vbase = Vp + v_off + h * 64;

    // ---- stage Q (128x64 tf32) via cp.async ----
    #pragma unroll
    for (int i = 0; i < 8; i++) {
        int idx = tid + i * 256; int r = idx >> 4, s = (idx & 15) * 4;
        cp16(s2u(&Ps[r * 68 + s]), qbase + (size_t)(b * S + q0 + r) * ld + s);
    }
    cp_commit();

    auto issue = [&](int st, int kt) {
        #pragma unroll
        for (int i = 0; i < 4; i++) {
            int idx = tid + i * 256;
            int r = idx >> 4, c = (idx & 15) * 4;
            size_t off = (size_t)(b * S + kt + r) * ld + c;
            cp16(s2u(&KVs[st * 8704 + r * 68 + c]), kbase + off);
            cp16(s2u(&KVs[st * 8704 + (64 + r) * 68 + c]), vbase + off);
        }
        if (tid < 16)
            cp16(s2u(&bsL[st * 64 + tid * 4]), bias + (size_t)b * S + kt + tid * 4);
        cp_commit();
    };

    issue(0, 0);
    cp_wait1();           // Q group retired
    __syncthreads();

    unsigned qf[8][4];
    int qr = warp * 16;
    #pragma unroll
    for (int ks = 0; ks < 8; ks++) {
        qf[ks][0] = Ps[(qr + g) * 68 + ks * 8 + tig];
        qf[ks][1] = Ps[(qr + g + 8) * 68 + ks * 8 + tig];
        qf[ks][2] = Ps[(qr + g) * 68 + ks * 8 + tig + 4];
        qf[ks][3] = Ps[(qr + g + 8) * 68 + ks * 8 + tig + 4];
    }

    float o[8][4];
    #pragma unroll
    for (int nt = 0; nt < 8; nt++)
        #pragma unroll
        for (int i = 0; i < 4; i++) o[nt][i] = 0.f;
    float m0 = -1e30f, m1 = -1e30f, l0 = 0.f, l1 = 0.f;
    const float sc = 0.125f * LOG2E;
    unsigned* pw = Ps + warp * 16 * 68;

    int ntile = S / 64;
    for (int t = 0; t < ntile; t++) {
        int st = t & 1;
        if (t + 1 < ntile) { issue(st ^ 1, (t + 1) * 64); cp_wait1(); }
        else               { cp_wait0(); }
        __syncthreads();

        const unsigned* KVf = KVs + st * 8704;
        const float* bsf = bsL + st * 64;

        float sa[8][4];
        #pragma unroll
        for (int nt = 0; nt < 8; nt++)
            #pragma unroll
            for (int i = 0; i < 4; i++) sa[nt][i] = 0.f;
        #pragma unroll
        for (int ks = 0; ks < 8; ks++) {
            unsigned bf[8][2];
            #pragma unroll
            for (int nt = 0; nt < 8; nt++) {
                bf[nt][0] = KVf[(nt * 8 + g) * 68 + ks * 8 + tig];
                bf[nt][1] = KVf[(nt * 8 + g) * 68 + ks * 8 + tig + 4];
            }
            #pragma unroll
            for (int nt = 0; nt < 8; nt++) mma8(sa[nt], qf[ks], bf[nt]);
        }

        float rm0 = -1e30f, rm1 = -1e30f;
        #pragma unroll
        for (int nt = 0; nt < 8; nt++) {
            float bl0 = bsf[nt * 8 + 2 * tig] * LOG2E;
            float bl1 = bsf[nt * 8 + 2 * tig + 1] * LOG2E;
            sa[nt][0] = sa[nt][0] * sc + bl0;
            sa[nt][1] = sa[nt][1] * sc + bl1;
            sa[nt][2] = sa[nt][2] * sc + bl0;
            sa[nt][3] = sa[nt][3] * sc + bl1;
            rm0 = fmaxf(rm0, fmaxf(sa[nt][0], sa[nt][1]));
            rm1 = fmaxf(rm1, fmaxf(sa[nt][2], sa[nt][3]));
        }
        rm0 = fmaxf(rm0, __shfl_xor_sync(0xffffffffu, rm0, 1));
        rm0 = fmaxf(rm0, __shfl_xor_sync(0xffffffffu, rm0, 2));
        rm1 = fmaxf(rm1, __shfl_xor_sync(0xffffffffu, rm1, 1));
        rm1 = fmaxf(rm1, __shfl_xor_sync(0xffffffffu, rm1, 2));
        float mn0 = fmaxf(m0, rm0), mn1 = fmaxf(m1, rm1);
        float c0 = ex2(m0 - mn0), c1 = ex2(m1 - mn1);
        float rs0 = 0.f, rs1 = 0.f;
        #pragma unroll
        for (int nt = 0; nt < 8; nt++) {
            sa[nt][0] = ex2(sa[nt][0] - mn0);
            sa[nt][1] = ex2(sa[nt][1] - mn0);
            sa[nt][2] = ex2(sa[nt][2] - mn1);
            sa[nt][3] = ex2(sa[nt][3] - mn1);
            rs0 += sa[nt][0] + sa[nt][1];
            rs1 += sa[nt][2] + sa[nt][3];
        }
        rs0 += __shfl_xor_sync(0xffffffffu, rs0, 1);
        rs0 += __shfl_xor_sync(0xffffffffu, rs0, 2);
        rs1 += __shfl_xor_sync(0xffffffffu, rs1, 1);
        rs1 += __shfl_xor_sync(0xffffffffu, rs1, 2);
        l0 = l0 * c0 + rs0; l1 = l1 * c1 + rs1;
        m0 = mn0; m1 = mn1;
        #pragma unroll
        for (int nt = 0; nt < 8; nt++) {
            o[nt][0] *= c0; o[nt][1] *= c0; o[nt][2] *= c1; o[nt][3] *= c1;
        }

        #pragma unroll
        for (int nt = 0; nt < 8; nt++) {
            int cc = nt * 8 + 2 * tig;
            pw[g * 68 + cc]           = f2tf(sa[nt][0]);
            pw[g * 68 + cc + 1]       = f2tf(sa[nt][1]);
            pw[(g + 8) * 68 + cc]     = f2tf(sa[nt][2]);
            pw[(g + 8) * 68 + cc + 1] = f2tf(sa[nt][3]);
        }
        __syncwarp();

        #pragma unroll
        for (int ks = 0; ks < 8; ks++) {
            unsigned af[4];
            af[0] = pw[g * 68 + ks * 8 + tig];
            af[1] = pw[(g + 8) * 68 + ks * 8 + tig];
            af[2] = pw[g * 68 + ks * 8 + tig + 4];
            af[3] = pw[(g + 8) * 68 + ks * 8 + tig + 4];
            #pragma unroll
            for (int nt = 0; nt < 8; nt++) {
                unsigned bf2[2];
                bf2[0] = KVf[(64 + ks * 8 + tig) * 68 + nt * 8 + g];
                bf2[1] = KVf[(64 + ks * 8 + tig + 4) * 68 + nt * 8 + g];
                mma8(o[nt], af, bf2);
            }
        }
        __syncthreads();
    }

    // ---- normalize + write ----
    float inv0 = 1.f / l0, inv1 = 1.f / l1;
    int row0 = b * S + q0 + warp * 16 + g;
    if (TF32OUT) {
        unsigned* ou0 = (unsigned*)Opv + o_off + h * 64 + (size_t)row0 * o_ld;
        unsigned* ou1 = (unsigned*)Opv + o_off + h * 64 + (size_t)(row0 + 8) * o_ld;
        #pragma unroll
        for (int nt = 0; nt < 8; nt++) {
            int col = nt * 8 + 2 * tig;
            *(uint2*)(ou0 + col) = make_uint2(f2tf(o[nt][0] * inv0), f2tf(o[nt][1] * inv0));
            *(uint2*)(ou1 + col) = make_uint2(f2tf(o[nt][2] * inv1), f2tf(o[nt][3] * inv1));
        }
    } else {
        float* ob0 = (float*)Opv + o_off + h * 64 + (size_t)row0 * o_ld;
        float* ob1 = (float*)Opv + o_off + h * 64 + (size_t)(row0 + 8) * o_ld;
        #pragma unroll
        for (int nt = 0; nt < 8; nt++) {
            int col = nt * 8 + 2 * tig;
            *(float2*)(ob0 + col) = make_float2(o[nt][0] * inv0, o[nt][1] * inv0);
            *(float2*)(ob1 + col) = make_float2(o[nt][2] * inv1, o[nt][3] * inv1);
        }
    }
}

// ---------------------------------------------------------------------------
// Fused survival MLPs, 8 tokens per block (fp32 input h1)
// ---------------------------------------------------------------------------
__global__ __launch_bounds__(128) void mlp_surv2(
    const float* __restrict__ H, const int* __restrict__ mask,
    const float* __restrict__ nw1, const float* __restrict__ nb1,
    const float* __restrict__ nw2, const float* __restrict__ nb2,
    const float* __restrict__ mw1, const float* __restrict__ mb1,
    const float* __restrict__ mw2, const float* __restrict__ mb2,
    const float* __restrict__ dw1, const float* __restrict__ db1,
    const float* __restrict__ dw2, const float* __restrict__ db2,
    float* __restrict__ biasM)
{
    __shared__ float hs[8][256];
    __shared__ float red[24][128];

    int t = threadIdx.x;
    int tok0 = blockIdx.x * 8;

    #pragma unroll
    for (int i = 0; i < 16; i++) {
        int idx = t + i * 128; int tk = idx >> 8, c = idx & 255;
        hs[tk][c] = H[(size_t)(tok0 + tk) * 256 + c];
    }
    __syncthreads();

    const float* wn = nw1 + (size_t)t * 256;
    const float* wm = mw1 + (size_t)t * 256;
    const float* wd = dw1 + (size_t)t * 256;
    float sn[8], smu2[8], sd[8];
    #pragma unroll
    for (int k = 0; k < 8; k++) { sn[k] = 0.f; smu2[k] = 0.f; sd[k] = 0.f; }
    for (int i = 0; i < 256; i++) {
        float a = wn[i], bb = wm[i], c = wd[i];
        #pragma unroll
        for (int k = 0; k < 8; k++) {
            float hv = hs[k][i];
            sn[k] += a * hv; smu2[k] += bb * hv; sd[k] += c * hv;
        }
    }
    float a1 = nb1[t], a2 = nw2[t], b1 = mb1[t], b2 = mw2[t], c1 = db1[t], c2 = dw2[t];
    #pragma unroll
    for (int k = 0; k < 8; k++) {
        red[k][t]      = fmaxf(sn[k]   + a1, 0.f) * a2;
        red[8 + k][t]  = fmaxf(smu2[k] + b1, 0.f) * b2;
        red[16 + k][t] = fmaxf(sd[k]   + c1, 0.f) * c2;
    }
    __syncthreads();

    for (int s2 = 64; s2 > 0; s2 >>= 1) {
        for (int j = t; j < 24 * s2; j += 128) {
            int row = j / s2, c = j % s2;
            red[row][c] += red[row][c + s2];
        }
        __syncthreads();
    }

    if (t < 8) {
        float zn = red[t][0] + nb2[0];
        float zm = red[8 + t][0] + mb2[0];
        float zd = red[16 + t][0] + db2[0];
        float n     = (zn > 20.f) ? zn : log1pf(__expf(zn));
        float mu    = 1.f / (1.f + __expf(-zm));
        float delta = fmaxf(zd, 0.f);
        float surv  = logf(n + 1e-8f) + logf(mu + 1e-8f) - delta;
        biasM[tok0 + t] = 0.1f * surv + ((mask[tok0 + t] > 0) ? 0.f : -1e9f);
    }
}

// ---------------------------------------------------------------------------
// Launch
// ---------------------------------------------------------------------------
extern "C" void kernel_launch(void* const* d_in, const int* in_sizes, int n_in,
                              void* d_out, int out_size)
{
    const float* x        = (const float*)d_in[0];
    const int*   mask     = (const int*)  d_in[1];
    const float* qw = (const float*)d_in[2],  *qb = (const float*)d_in[3];
    const float* kw = (const float*)d_in[4],  *kb = (const float*)d_in[5];
    const float* vw = (const float*)d_in[6],  *vb = (const float*)d_in[7];
    const float* ow = (const float*)d_in[8],  *ob = (const float*)d_in[9];
    const float* sp_w = (const float*)d_in[10], *sp_b = (const float*)d_in[11];
    const float* sa_in_w  = (const float*)d_in[12], *sa_in_b  = (const float*)d_in[13];
    const float* sa_out_w = (const float*)d_in[14], *sa_out_b = (const float*)d_in[15];
    const float* nw1 = (const float*)d_in[16], *nb1 = (const float*)d_in[17];
    const float* nw2 = (const float*)d_in[18], *nb2 = (const float*)d_in[19];
    const float* mw1 = (const float*)d_in[20], *mb1 = (const float*)d_in[21];
    const float* mw2 = (const float*)d_in[22], *mb2 = (const float*)d_in[23];
    const float* dw1 = (const float*)d_in[24], *db1 = (const float*)d_in[25];
    const float* dw2 = (const float*)d_in[26], *db2 = (const float*)d_in[27];
    float* out = (float*)d_out;

    unsigned *xtf, *qwtf, *kwtf, *vwtf, *owtf, *spwtf, *saiwtf, *saowtf;
    unsigned *Q, *K, *V, *qkvs, *h0, *sattn, *attn;
    float *h1, *biasS, *biasM;
    cudaGetSymbolAddress((void**)&xtf,    g_xtf);
    cudaGetSymbolAddress((void**)&qwtf,   g_qwtf);
    cudaGetSymbolAddress((void**)&kwtf,   g_kwtf);
    cudaGetSymbolAddress((void**)&vwtf,   g_vwtf);
    cudaGetSymbolAddress((void**)&owtf,   g_owtf);
    cudaGetSymbolAddress((void**)&spwtf,  g_spwtf);
    cudaGetSymbolAddress((void**)&saiwtf, g_saiwtf);
    cudaGetSymbolAddress((void**)&saowtf, g_saowtf);
    cudaGetSymbolAddress((void**)&Q,      g_Q);
    cudaGetSymbolAddress((void**)&K,      g_K);
    cudaGetSymbolAddress((void**)&V,      g_V);
    cudaGetSymbolAddress((void**)&attn,   g_attn);
    cudaGetSymbolAddress((void**)&h0,     g_h0);
    cudaGetSymbolAddress((void**)&qkvs,   g_qkvs);
    cudaGetSymbolAddress((void**)&sattn,  g_sattn);
    cudaGetSymbolAddress((void**)&h1,     g_h1);
    cudaGetSymbolAddress((void**)&biasS,  g_biasS);
    cudaGetSymbolAddress((void**)&biasM,  g_biasM);

    const int M = MTOK, S = SEQ, B = BATCH, H = HDIM, I = IDIM;

    const int SM128 = (2 * 128 * 36 + 2 * 128 * 36) * 4;   // 73728
    const int SM64  = (2 * 64 * 36 + 2 * 128 * 36) * 4;    // 55296
    const int SMATT = (3 * 8704 + 128) * 4;                // 104960

    static cudaStream_t s1 = nullptr;
    static cudaEvent_t eFork = nullptr, eJoin = nullptr;
    static bool init_done = false, use_streams = false;
    if (!init_done) {
        use_streams =
            (cudaStreamCreateWithFlags(&s1, cudaStreamNonBlocking) == cudaSuccess) &&
            (cudaEventCreateWithFlags(&eFork, cudaEventDisableTiming) == cudaSuccess) &&
            (cudaEventCreateWithFlags(&eJoin, cudaEventDisableTiming) == cudaSuccess);
        cudaFuncSetAttribute((const void*)gemm_u<128, false>, cudaFuncAttributeMaxDynamicSharedMemorySize, SM128);
        cudaFuncSetAttribute((const void*)gemm_u<128, true>,  cudaFuncAttributeMaxDynamicSharedMemorySize, SM128);
        cudaFuncSetAttribute((const void*)gemm_u_qkv,         cudaFuncAttributeMaxDynamicSharedMemorySize, SM128);
        cudaFuncSetAttribute((const void*)gemm_u<64, false>,  cudaFuncAttributeMaxDynamicSharedMemorySize, SM64);
        cudaFuncSetAttribute((const void*)gemm_u<64, true>,   cudaFuncAttributeMaxDynamicSharedMemorySize, SM64);
        cudaFuncSetAttribute((const void*)attn5<false>,       cudaFuncAttributeMaxDynamicSharedMemorySize, SMATT);
        cudaFuncSetAttribute((const void*)attn5<true>,        cudaFuncAttributeMaxDynamicSharedMemorySize, SMATT);
        init_done = true;
    }

    // 0) convert x + all weights to tf32 bits (both branches depend on this)
    cvt_tf32_all<<<dim3(512, 8), 256>>>(x, qw, kw, vw, ow, sp_w, sa_in_w, sa_out_w,
                                        xtf, qwtf, kwtf, vwtf, owtf, spwtf, saiwtf, saowtf);

    if (use_streams) {
        cudaEventRecord(eFork, 0);
        cudaStreamWaitEvent(s1, eFork, 0);
        gemm_u_qkv<<<dim3(H / 128, M / 128, 3), 256, SM128, s1>>>(
            xtf, qwtf, kwtf, vwtf, qb, kb, vb, Q, K, V, M, H, H);
        cudaEventRecord(eJoin, s1);
    } else {
        gemm_u_qkv<<<dim3(H / 128, M / 128, 3), 256, SM128>>>(
            xtf, qwtf, kwtf, vwtf, qb, kb, vb, Q, K, V, M, H, H);
    }

    // scorer chain on default stream (concurrent with QKV when streams work)
    mask_bias_kernel<<<(M + 255) / 256, 256>>>(mask, biasS, M);
    gemm_u<64, true><<<dim3(I / 128, M / 64), 256, SM64>>>(xtf, spwtf, sp_b, h0, M, I, H);
    gemm_u<128, true><<<dim3(3 * I / 128, M / 128), 256, SM128>>>(h0, saiwtf, sa_in_b, qkvs, M, 3 * I, I);
    attn5<true><<<dim3(S / 128, 4, B), 256, SMATT>>>(qkvs, qkvs, qkvs, biasS, sattn,
                                                     S, 3 * I, 0, I, 2 * I, I, 0);
    gemm_u<64, false><<<dim3(I / 128, M / 64), 256, SM64>>>(sattn, saowtf, sa_out_b, h1, M, I, I);
    mlp_surv2<<<M / 8, 128>>>(h1, mask, nw1, nb1, nw2, nb2,
                              mw1, mb1, mw2, mb2, dw1, db1, dw2, db2, biasM);

    // join, then main attention + output projection
    if (use_streams) cudaStreamWaitEvent(0, eJoin, 0);
    attn5<true><<<dim3(S / 128, 12, B), 256, SMATT>>>(Q, K, V, biasM, attn,
                                                      S, H, 0, 0, 0, H, 0);
    gemm_u<128, false><<<dim3(H / 128, M / 128), 256, SM128>>>(attn, owtf, ob, out, M, H, H);
}